// round 4
// baseline (speedup 1.0000x reference)
#include <cuda_runtime.h>
#include <cuda_bf16.h>
#include <math.h>

// ---------------------------------------------------------------------------
// Problem constants
//   B=2, S=2048, H=2048, NH=16, QL=1536, KVL=512, NOPE=128, ROPE=64, VD=128
//   QKH=192, scale = 1/sqrt(192)
// ---------------------------------------------------------------------------
#define SCALE_QK 0.07216878364870323f
#define ROPE_LF  0.28782313662425574f   /* ln(10000)/32 */

// ---------------------------------------------------------------------------
// Device scratch (static globals — no runtime allocation)
// ---------------------------------------------------------------------------
__device__ float g_qa [(size_t)4096 * 1536];          // x @ wq_a^T + b
__device__ float g_qn [(size_t)4096 * 1536];          // rmsnorm(qa)
__device__ float g_q  [(size_t)4096 * 3072];          // qn @ wq_b^T + b
__device__ float g_kvf[(size_t)4096 * 576];           // x @ wkv_a^T + b
__device__ float g_kc [(size_t)4096 * 576];           // [norm(kv) | rope(k_pe)]
__device__ float g_kvT[(size_t)2 * 512 * 2048];       // per-batch V^T
__device__ float g_wbt[(size_t)16 * 512 * 128];       // wkv_b[:, :128] -> [h][c][d]
__device__ float g_qc [(size_t)32 * 2048 * 576];      // scaled [q_lat | rope(q_pe)]
__device__ float g_sc [(size_t)32 * 2048 * 2048];     // scores / probs
__device__ float g_ol [(size_t)32 * 2048 * 512];      // attn @ V
__device__ float g_oh [(size_t)4096 * 2048];          // per-head out, concat

// ---------------------------------------------------------------------------
// Generic NT SGEMM:  C[m,n] = alpha * sum_k A[m,k]*B[n,k]  (+ bias[n])
// Both A and B are row-major with K contiguous. Batched over blockIdx.z with
// z -> (b = z>>4, h = z&15) strides. Requires: M,N % 64 == 0, K % 16 == 0,
// all ld % 4 == 0 (true for every call here).
// flags bit0: causal tile skip (skip when bn0 >= bm0+64)
// flags bit1: K limited to min(K, bm0+64)  (attn@V causal K clamp)
// ---------------------------------------------------------------------------
__global__ void __launch_bounds__(256)
sgemm_nt(const float* __restrict__ A, int lda, long long sAb, long long sAh,
         const float* __restrict__ B, int ldb, long long sBb, long long sBh,
         float* __restrict__ C, int ldc, long long sCb, long long sCh,
         int K, const float* __restrict__ bias, float alpha, int flags)
{
    const long long zb = blockIdx.z >> 4;
    const long long zh = blockIdx.z & 15;
    const int bm0 = blockIdx.y * 64;
    const int bn0 = blockIdx.x * 64;
    if ((flags & 1) && bn0 >= bm0 + 64) return;
    const int Kl = (flags & 2) ? min(K, bm0 + 64) : K;

    A += zb * sAb + zh * sAh + (long long)bm0 * lda;
    B += zb * sBb + zh * sBh + (long long)bn0 * ldb;
    C += zb * sCb + zh * sCh + (long long)bm0 * ldc + bn0;

    __shared__ float As[16][68];
    __shared__ float Bs[16][68];

    const int tid = threadIdx.x;
    const int tx4 = (tid & 15) * 4;
    const int ty4 = (tid >> 4) * 4;
    const int lr  = tid >> 2;          // 0..63 : tile row loaded by this thread
    const int lk  = (tid & 3) * 4;     // 0,4,8,12 : k offset within 16

    const float* Ag = A + (long long)lr * lda + lk;
    const float* Bg = B + (long long)lr * ldb + lk;

    float acc[4][4] = {};

    for (int k0 = 0; k0 < Kl; k0 += 16) {
        float4 a4 = *(const float4*)(Ag + k0);
        float4 b4 = *(const float4*)(Bg + k0);
        As[lk + 0][lr] = a4.x; As[lk + 1][lr] = a4.y;
        As[lk + 2][lr] = a4.z; As[lk + 3][lr] = a4.w;
        Bs[lk + 0][lr] = b4.x; Bs[lk + 1][lr] = b4.y;
        Bs[lk + 2][lr] = b4.z; Bs[lk + 3][lr] = b4.w;
        __syncthreads();
#pragma unroll
        for (int k = 0; k < 16; ++k) {
            float4 ra = *(const float4*)&As[k][ty4];
            float4 rb = *(const float4*)&Bs[k][tx4];
            acc[0][0] += ra.x * rb.x; acc[0][1] += ra.x * rb.y;
            acc[0][2] += ra.x * rb.z; acc[0][3] += ra.x * rb.w;
            acc[1][0] += ra.y * rb.x; acc[1][1] += ra.y * rb.y;
            acc[1][2] += ra.y * rb.z; acc[1][3] += ra.y * rb.w;
            acc[2][0] += ra.z * rb.x; acc[2][1] += ra.z * rb.y;
            acc[2][2] += ra.z * rb.z; acc[2][3] += ra.z * rb.w;
            acc[3][0] += ra.w * rb.x; acc[3][1] += ra.w * rb.y;
            acc[3][2] += ra.w * rb.z; acc[3][3] += ra.w * rb.w;
        }
        __syncthreads();
    }

    float4 bv = make_float4(0.f, 0.f, 0.f, 0.f);
    if (bias) bv = *(const float4*)(bias + bn0 + tx4);
#pragma unroll
    for (int i = 0; i < 4; ++i) {
        float4 o;
        o.x = alpha * acc[i][0] + bv.x;
        o.y = alpha * acc[i][1] + bv.y;
        o.z = alpha * acc[i][2] + bv.z;
        o.w = alpha * acc[i][3] + bv.w;
        *(float4*)(C + (long long)(ty4 + i) * ldc + tx4) = o;
    }
}

// ---------------------------------------------------------------------------
// rmsnorm over QL=1536 (g_qa -> g_qn)
// ---------------------------------------------------------------------------
__global__ void rmsnorm_q_kernel(const float* __restrict__ w)
{
    const int t = blockIdx.x;
    const float* x = g_qa + (size_t)t * 1536;
    float* y = g_qn + (size_t)t * 1536;
    float v[6];
    float ss = 0.f;
#pragma unroll
    for (int i = 0; i < 6; ++i) {
        v[i] = x[threadIdx.x + i * 256];
        ss += v[i] * v[i];
    }
    __shared__ float sh[8];
    __shared__ float bc;
    for (int o = 16; o; o >>= 1) ss += __shfl_xor_sync(0xffffffffu, ss, o);
    if ((threadIdx.x & 31) == 0) sh[threadIdx.x >> 5] = ss;
    __syncthreads();
    if (threadIdx.x == 0) {
        float s2 = 0.f;
#pragma unroll
        for (int i = 0; i < 8; ++i) s2 += sh[i];
        bc = rsqrtf(s2 * (1.f / 1536.f) + 1e-6f);
    }
    __syncthreads();
    const float inv = bc;
#pragma unroll
    for (int i = 0; i < 6; ++i) {
        int j = threadIdx.x + i * 256;
        y[j] = w[j] * v[i] * inv;
    }
}

// ---------------------------------------------------------------------------
// kv prep: rmsnorm first 512 of g_kvf -> g_kc[:, :512] and g_kvT (transposed);
// rope last 64 -> g_kc[:, 512:576]
// ---------------------------------------------------------------------------
__global__ void kv_prep_kernel(const float* __restrict__ w)
{
    const int t = blockIdx.x;
    const int b = t >> 11, s = t & 2047;
    const float* x = g_kvf + (size_t)t * 576;
    const int j0 = threadIdx.x, j1 = threadIdx.x + 256;
    float v0 = x[j0], v1 = x[j1];
    float ss = v0 * v0 + v1 * v1;
    __shared__ float sh[8];
    __shared__ float bc;
    for (int o = 16; o; o >>= 1) ss += __shfl_xor_sync(0xffffffffu, ss, o);
    if ((threadIdx.x & 31) == 0) sh[threadIdx.x >> 5] = ss;
    __syncthreads();
    if (threadIdx.x == 0) {
        float s2 = 0.f;
#pragma unroll
        for (int i = 0; i < 8; ++i) s2 += sh[i];
        bc = rsqrtf(s2 * (1.f / 512.f) + 1e-6f);
    }
    __syncthreads();
    const float inv = bc;
    float* kc = g_kc + (size_t)t * 576;
    float a0 = w[j0] * v0 * inv;
    float a1 = w[j1] * v1 * inv;
    kc[j0] = a0;
    kc[j1] = a1;
    g_kvT[((size_t)b * 512 + j0) * 2048 + s] = a0;
    g_kvT[((size_t)b * 512 + j1) * 2048 + s] = a1;
    if (threadIdx.x < 32) {
        int i = threadIdx.x;
        float p1 = x[512 + i], p2 = x[544 + i];
        float th = (float)s * expf(-(float)i * ROPE_LF);
        float sn, cs;
        sincosf(th, &sn, &cs);
        kc[512 + i] = p1 * cs - p2 * sn;
        kc[544 + i] = p2 * cs + p1 * sn;
    }
}

// ---------------------------------------------------------------------------
// rope q_pe + scale, packed into g_qc[:, 512:576]   (4096*16*32 threads)
// ---------------------------------------------------------------------------
__global__ void qpe_pack_kernel()
{
    const int idx = blockIdx.x * 256 + threadIdx.x;
    const int i = idx & 31;
    const int h = (idx >> 5) & 15;
    const int t = idx >> 9;
    const int b = t >> 11, s = t & 2047;
    const float* qp = g_q + (size_t)t * 3072 + h * 192 + 128;
    float p1 = qp[i], p2 = qp[32 + i];
    float th = (float)s * expf(-(float)i * ROPE_LF);
    float sn, cs;
    sincosf(th, &sn, &cs);
    float* dst = g_qc + ((size_t)((b * 16 + h) * 2048 + s)) * 576 + 512;
    dst[i]      = (p1 * cs - p2 * sn) * SCALE_QK;
    dst[32 + i] = (p2 * cs + p1 * sn) * SCALE_QK;
}

// ---------------------------------------------------------------------------
// wkv_b[:, :128, :] -> g_wbt[h][c][d]   (16*512*128 threads)
// ---------------------------------------------------------------------------
__global__ void wbt_kernel(const float* __restrict__ w)
{
    const int idx = blockIdx.x * 256 + threadIdx.x;
    const int d = idx & 127;
    const int c = (idx >> 7) & 511;
    const int h = idx >> 16;
    g_wbt[idx] = w[((size_t)(h * 256 + d)) * 512 + c];
}

// ---------------------------------------------------------------------------
// causal softmax over scores rows (in place). 65536 rows of length s+1.
// Also zero-fills (s, tile_end) so the K-clamped attn@V GEMM reads valid zeros.
// ---------------------------------------------------------------------------
__global__ void softmax_kernel(const int* __restrict__ mask)
{
    const int rid = blockIdx.x;
    const int s = rid & 2047;
    const int b = rid >> 15;               // rid / (16*2048)
    float* row = g_sc + (size_t)rid * 2048;
    const int* mrow = mask + b * 2048;
    const int n = s + 1;
    const int tid = threadIdx.x;

    float x[8];
    float mx = -3.0e38f;
#pragma unroll
    for (int it = 0; it < 8; ++it) {
        int t = tid + it * 256;
        float v = -3.0e38f;
        if (t < n) v = row[t] + (mrow[t] == 0 ? -1e15f : 0.f);
        x[it] = v;
        mx = fmaxf(mx, v);
    }
    __shared__ float sh[8];
    __shared__ float bc;
    for (int o = 16; o; o >>= 1) mx = fmaxf(mx, __shfl_xor_sync(0xffffffffu, mx, o));
    if ((tid & 31) == 0) sh[tid >> 5] = mx;
    __syncthreads();
    if (tid == 0) {
        float m = sh[0];
#pragma unroll
        for (int i = 1; i < 8; ++i) m = fmaxf(m, sh[i]);
        bc = m;
    }
    __syncthreads();
    mx = bc;
    float sum = 0.f;
#pragma unroll
    for (int it = 0; it < 8; ++it) {
        x[it] = expf(x[it] - mx);
        sum += x[it];
    }
    for (int o = 16; o; o >>= 1) sum += __shfl_xor_sync(0xffffffffu, sum, o);
    if ((tid & 31) == 0) sh[tid >> 5] = sum;
    __syncthreads();
    if (tid == 0) {
        float s2 = 0.f;
#pragma unroll
        for (int i = 0; i < 8; ++i) s2 += sh[i];
        bc = 1.f / s2;
    }
    __syncthreads();
    const float rinv = bc;
    const int tend = (s & ~63) + 64;
#pragma unroll
    for (int it = 0; it < 8; ++it) {
        int t = tid + it * 256;
        if (t < n)            row[t] = x[it] * rinv;
        else if (t < tend)    row[t] = 0.f;
    }
}

// ---------------------------------------------------------------------------
// launch
// ---------------------------------------------------------------------------
extern "C" void kernel_launch(void* const* d_in, const int* in_sizes, int n_in,
                              void* d_out, int out_size)
{
    (void)in_sizes; (void)n_in; (void)out_size;
    const float* x        = (const float*)d_in[0];
    const int*   mask     = (const int*)  d_in[1];
    const float* wq_a_w   = (const float*)d_in[2];
    const float* wq_a_b   = (const float*)d_in[3];
    const float* q_norm_w = (const float*)d_in[4];
    const float* wq_b_w   = (const float*)d_in[5];
    const float* wq_b_b   = (const float*)d_in[6];
    const float* wkv_a_w  = (const float*)d_in[7];
    const float* wkv_a_b  = (const float*)d_in[8];
    const float* kv_norm_w= (const float*)d_in[9];
    const float* wkv_b_w  = (const float*)d_in[10];
    const float* wo_w     = (const float*)d_in[11];
    const float* wo_b     = (const float*)d_in[12];
    float* out = (float*)d_out;

    float *qa, *qn, *q, *kvf, *kc, *kvT, *wbt, *qc, *sc, *ol, *oh;
    cudaGetSymbolAddress((void**)&qa,  g_qa);
    cudaGetSymbolAddress((void**)&qn,  g_qn);
    cudaGetSymbolAddress((void**)&q,   g_q);
    cudaGetSymbolAddress((void**)&kvf, g_kvf);
    cudaGetSymbolAddress((void**)&kc,  g_kc);
    cudaGetSymbolAddress((void**)&kvT, g_kvT);
    cudaGetSymbolAddress((void**)&wbt, g_wbt);
    cudaGetSymbolAddress((void**)&qc,  g_qc);
    cudaGetSymbolAddress((void**)&sc,  g_sc);
    cudaGetSymbolAddress((void**)&ol,  g_ol);
    cudaGetSymbolAddress((void**)&oh,  g_oh);

    const dim3 blk(256);

    // q_a = x @ wq_a^T + b                         [4096,1536]
    sgemm_nt<<<dim3(24, 64, 1), blk>>>(x, 2048, 0, 0, wq_a_w, 2048, 0, 0,
                                       qa, 1536, 0, 0, 2048, wq_a_b, 1.f, 0);
    // rmsnorm
    rmsnorm_q_kernel<<<4096, 256>>>(q_norm_w);
    // q = qn @ wq_b^T + b                          [4096,3072]
    sgemm_nt<<<dim3(48, 64, 1), blk>>>(qn, 1536, 0, 0, wq_b_w, 1536, 0, 0,
                                       q, 3072, 0, 0, 1536, wq_b_b, 1.f, 0);
    // kv_full = x @ wkv_a^T + b                    [4096,576]
    sgemm_nt<<<dim3(9, 64, 1), blk>>>(x, 2048, 0, 0, wkv_a_w, 2048, 0, 0,
                                      kvf, 576, 0, 0, 2048, wkv_a_b, 1.f, 0);
    // kv rmsnorm + k_pe rope -> kc, kvT
    kv_prep_kernel<<<4096, 256>>>(kv_norm_w);
    // wkv_b nope-transpose
    wbt_kernel<<<4096, 256>>>(wkv_b_w);
    // q_pe rope + scale into qc[:,512:576]
    qpe_pack_kernel<<<8192, 256>>>();
    // q_lat = q_nope @ wkv_b[:, :128]^T  (scaled)  -> qc[:, :512]
    sgemm_nt<<<dim3(8, 32, 32), blk>>>(
        q, 3072, (long long)2048 * 3072, 192,
        wbt, 128, 0, (long long)512 * 128,
        qc, 576, (long long)16 * 2048 * 576, (long long)2048 * 576,
        128, nullptr, SCALE_QK, 0);
    // scores = Qc @ Kc^T  (causal tile skip)
    sgemm_nt<<<dim3(32, 32, 32), blk>>>(
        qc, 576, (long long)16 * 2048 * 576, (long long)2048 * 576,
        kc, 576, (long long)2048 * 576, 0,
        sc, 2048, (long long)16 * 2048 * 2048, (long long)2048 * 2048,
        576, nullptr, 1.f, 1);
    // softmax (causal + mask)
    softmax_kernel<<<65536, 256>>>(mask);
    // out_lat = P @ V  (K clamped per query tile)
    sgemm_nt<<<dim3(8, 32, 32), blk>>>(
        sc, 2048, (long long)16 * 2048 * 2048, (long long)2048 * 2048,
        kvT, 2048, (long long)512 * 2048, 0,
        ol, 512, (long long)16 * 2048 * 512, (long long)2048 * 512,
        2048, nullptr, 1.f, 2);
    // out_head[t, h*128+d] = out_lat @ wkv_b[:, 128:]^T
    sgemm_nt<<<dim3(2, 32, 32), blk>>>(
        ol, 512, (long long)16 * 2048 * 512, (long long)2048 * 512,
        wkv_b_w + 128 * 512, 512, 0, (long long)256 * 512,
        oh, 2048, (long long)2048 * 2048, 128,
        512, nullptr, 1.f, 0);
    // out = out_head @ wo^T + b
    sgemm_nt<<<dim3(32, 64, 1), blk>>>(oh, 2048, 0, 0, wo_w, 2048, 0, 0,
                                       out, 2048, 0, 0, 2048, wo_b, 1.f, 0);
}

// round 8
// speedup vs baseline: 2.4676x; 2.4676x over previous
#include <cuda_runtime.h>
#include <cuda_bf16.h>
#include <math.h>

// ---------------------------------------------------------------------------
// Problem constants
//   B=2, S=2048, H=2048, NH=16, QL=1536, KVL=512, NOPE=128, ROPE=64, VD=128
//   QKH=192, scale = 1/sqrt(192)
// ---------------------------------------------------------------------------
#define SCALE_QK 0.07216878364870323f
#define ROPE_LF  0.28782313662425574f   /* ln(10000)/32 */

// ---------------------------------------------------------------------------
// Device scratch (static globals — no runtime allocation)
// ---------------------------------------------------------------------------
__device__ float g_qa [(size_t)4096 * 1536];          // x @ wq_a^T + b
__device__ float g_qn [(size_t)4096 * 1536];          // rmsnorm(qa)
__device__ float g_q  [(size_t)4096 * 3072];          // qn @ wq_b^T + b
__device__ float g_kvf[(size_t)4096 * 576];           // x @ wkv_a^T + b
__device__ float g_kc [(size_t)4096 * 576];           // [norm(kv) | rope(k_pe)]
__device__ float g_kvT[(size_t)2 * 512 * 2048];       // per-batch V^T
__device__ float g_wbt[(size_t)16 * 512 * 128];       // wkv_b[:, :128] -> [h][c][d]
__device__ float g_qc [(size_t)32 * 2048 * 576];      // scaled [q_lat | rope(q_pe)]
__device__ float g_sc [(size_t)32 * 2048 * 2048];     // scores / probs
__device__ float g_ol [(size_t)32 * 2048 * 512];      // attn @ V
__device__ float g_oh [(size_t)4096 * 2048];          // per-head out, concat

// ---------------------------------------------------------------------------
// TF32 helpers
// ---------------------------------------------------------------------------
__device__ __forceinline__ unsigned f2tf32(float x) {
    unsigned r;
    asm("cvt.rna.tf32.f32 %0, %1;" : "=r"(r) : "f"(x));
    return r;
}

// ---------------------------------------------------------------------------
// TF32 tensor-core NT GEMM:  C[m,n] = alpha * sum_k A[m,k]*B[n,k] (+ bias[n])
// A,B row-major K-contiguous. CTA tile 128x128, BK=16, 256 threads
// (8 warps, 2x4 grid of 64x32 warp tiles), mma.m16n8k8.tf32, double-buffered.
// Requires: M % 128 == 0, K % 16 == 0, lda/ldb/ldc % 4 == 0 (all true here).
// N may be ragged (guarded B loads / C stores).
// flags bit0: causal tile skip (skip when bn0 >= bm0+128)
// flags bit1: K clamped to min(K, bm0+128)  (attn@V causal K clamp)
// ---------------------------------------------------------------------------
#define BM 128
#define BN 128
#define BK 16
#define SPAD 4

__global__ void __launch_bounds__(256)
gemm_tf32(const float* __restrict__ A, int lda, long long sAb, long long sAh,
          const float* __restrict__ B, int ldb, long long sBb, long long sBh,
          float* __restrict__ C, int ldc, long long sCb, long long sCh,
          int N, int K, const float* __restrict__ bias, float alpha, int flags)
{
    const long long zb = blockIdx.z >> 4;
    const long long zh = blockIdx.z & 15;
    const int bm0 = blockIdx.y * BM;
    const int bn0 = blockIdx.x * BN;
    if ((flags & 1) && bn0 >= bm0 + BM) return;
    const int Kl = (flags & 2) ? min(K, bm0 + BM) : K;

    A += zb * sAb + zh * sAh + (long long)bm0 * lda;
    B += zb * sBb + zh * sBh + (long long)bn0 * ldb;
    C += zb * sCb + zh * sCh;

    __shared__ float As[2][BK][BM + SPAD];
    __shared__ float Bs[2][BK][BN + SPAD];

    const int tid  = threadIdx.x;
    const int lane = tid & 31;
    const int warp = tid >> 5;
    const int wm   = warp >> 2;        // 0..1
    const int wn   = warp & 3;         // 0..3
    const int lq   = lane >> 2;        // 0..7
    const int lr   = lane & 3;         // 0..3

    const int lm = tid >> 2;           // 0..63 : tile row this thread loads
    const int lk = (tid & 3) * 4;      // 0,4,8,12

    const float* Ag0 = A + (long long)lm * lda + lk;
    const float* Ag1 = Ag0 + (long long)64 * lda;
    const bool bv0 = (bn0 + lm)      < N;
    const bool bv1 = (bn0 + lm + 64) < N;
    const float* Bg0 = B + (long long)lm * ldb + lk;
    const float* Bg1 = Bg0 + (long long)64 * ldb;

    float acc[4][4][4];
#pragma unroll
    for (int i = 0; i < 4; ++i)
#pragma unroll
        for (int j = 0; j < 4; ++j)
#pragma unroll
            for (int r = 0; r < 4; ++r) acc[i][j][r] = 0.f;

    const int nK = Kl / BK;
    const float4 z4 = make_float4(0.f, 0.f, 0.f, 0.f);

    float4 ra0 = *(const float4*)(Ag0);
    float4 ra1 = *(const float4*)(Ag1);
    float4 rb0 = bv0 ? *(const float4*)(Bg0) : z4;
    float4 rb1 = bv1 ? *(const float4*)(Bg1) : z4;

    // stage 0
    As[0][lk + 0][lm] = __uint_as_float(f2tf32(ra0.x));
    As[0][lk + 1][lm] = __uint_as_float(f2tf32(ra0.y));
    As[0][lk + 2][lm] = __uint_as_float(f2tf32(ra0.z));
    As[0][lk + 3][lm] = __uint_as_float(f2tf32(ra0.w));
    As[0][lk + 0][lm + 64] = __uint_as_float(f2tf32(ra1.x));
    As[0][lk + 1][lm + 64] = __uint_as_float(f2tf32(ra1.y));
    As[0][lk + 2][lm + 64] = __uint_as_float(f2tf32(ra1.z));
    As[0][lk + 3][lm + 64] = __uint_as_float(f2tf32(ra1.w));
    Bs[0][lk + 0][lm] = __uint_as_float(f2tf32(rb0.x));
    Bs[0][lk + 1][lm] = __uint_as_float(f2tf32(rb0.y));
    Bs[0][lk + 2][lm] = __uint_as_float(f2tf32(rb0.z));
    Bs[0][lk + 3][lm] = __uint_as_float(f2tf32(rb0.w));
    Bs[0][lk + 0][lm + 64] = __uint_as_float(f2tf32(rb1.x));
    Bs[0][lk + 1][lm + 64] = __uint_as_float(f2tf32(rb1.y));
    Bs[0][lk + 2][lm + 64] = __uint_as_float(f2tf32(rb1.z));
    Bs[0][lk + 3][lm + 64] = __uint_as_float(f2tf32(rb1.w));
    __syncthreads();

    for (int kt = 0; kt < nK; ++kt) {
        const int buf = kt & 1;
        if (kt + 1 < nK) {
            const int k0 = (kt + 1) * BK;
            ra0 = *(const float4*)(Ag0 + k0);
            ra1 = *(const float4*)(Ag1 + k0);
            rb0 = bv0 ? *(const float4*)(Bg0 + k0) : z4;
            rb1 = bv1 ? *(const float4*)(Bg1 + k0) : z4;
        }
#pragma unroll
        for (int kb = 0; kb < BK; kb += 8) {
            unsigned af[4][4], bf[4][2];
#pragma unroll
            for (int ni = 0; ni < 4; ++ni) {
                const int n0 = wn * 32 + ni * 8 + lq;
                bf[ni][0] = __float_as_uint(Bs[buf][kb + lr][n0]);
                bf[ni][1] = __float_as_uint(Bs[buf][kb + 4 + lr][n0]);
            }
#pragma unroll
            for (int mi = 0; mi < 4; ++mi) {
                const int m0 = wm * 64 + mi * 16 + lq;
                af[mi][0] = __float_as_uint(As[buf][kb + lr][m0]);
                af[mi][1] = __float_as_uint(As[buf][kb + lr][m0 + 8]);
                af[mi][2] = __float_as_uint(As[buf][kb + 4 + lr][m0]);
                af[mi][3] = __float_as_uint(As[buf][kb + 4 + lr][m0 + 8]);
            }
#pragma unroll
            for (int mi = 0; mi < 4; ++mi)
#pragma unroll
                for (int ni = 0; ni < 4; ++ni) {
                    asm volatile(
                        "mma.sync.aligned.m16n8k8.row.col.f32.tf32.tf32.f32 "
                        "{%0,%1,%2,%3}, {%4,%5,%6,%7}, {%8,%9}, {%0,%1,%2,%3};\n"
                        : "+f"(acc[mi][ni][0]), "+f"(acc[mi][ni][1]),
                          "+f"(acc[mi][ni][2]), "+f"(acc[mi][ni][3])
                        : "r"(af[mi][0]), "r"(af[mi][1]),
                          "r"(af[mi][2]), "r"(af[mi][3]),
                          "r"(bf[ni][0]), "r"(bf[ni][1]));
                }
        }
        if (kt + 1 < nK) {
            const int nb = (kt + 1) & 1;
            As[nb][lk + 0][lm] = __uint_as_float(f2tf32(ra0.x));
            As[nb][lk + 1][lm] = __uint_as_float(f2tf32(ra0.y));
            As[nb][lk + 2][lm] = __uint_as_float(f2tf32(ra0.z));
            As[nb][lk + 3][lm] = __uint_as_float(f2tf32(ra0.w));
            As[nb][lk + 0][lm + 64] = __uint_as_float(f2tf32(ra1.x));
            As[nb][lk + 1][lm + 64] = __uint_as_float(f2tf32(ra1.y));
            As[nb][lk + 2][lm + 64] = __uint_as_float(f2tf32(ra1.z));
            As[nb][lk + 3][lm + 64] = __uint_as_float(f2tf32(ra1.w));
            Bs[nb][lk + 0][lm] = __uint_as_float(f2tf32(rb0.x));
            Bs[nb][lk + 1][lm] = __uint_as_float(f2tf32(rb0.y));
            Bs[nb][lk + 2][lm] = __uint_as_float(f2tf32(rb0.z));
            Bs[nb][lk + 3][lm] = __uint_as_float(f2tf32(rb0.w));
            Bs[nb][lk + 0][lm + 64] = __uint_as_float(f2tf32(rb1.x));
            Bs[nb][lk + 1][lm + 64] = __uint_as_float(f2tf32(rb1.y));
            Bs[nb][lk + 2][lm + 64] = __uint_as_float(f2tf32(rb1.z));
            Bs[nb][lk + 3][lm + 64] = __uint_as_float(f2tf32(rb1.w));
        }
        __syncthreads();
    }

    // epilogue
#pragma unroll
    for (int mi = 0; mi < 4; ++mi) {
        const int r0 = bm0 + wm * 64 + mi * 16 + lq;
#pragma unroll
        for (int ni = 0; ni < 4; ++ni) {
            const int c0 = bn0 + wn * 32 + ni * 8 + 2 * lr;
            if (c0 < N) {
                float b0 = 0.f, b1 = 0.f;
                if (bias) { b0 = bias[c0]; b1 = bias[c0 + 1]; }
                float2 v;
                v.x = alpha * acc[mi][ni][0] + b0;
                v.y = alpha * acc[mi][ni][1] + b1;
                *(float2*)(C + (long long)r0 * ldc + c0) = v;
                v.x = alpha * acc[mi][ni][2] + b0;
                v.y = alpha * acc[mi][ni][3] + b1;
                *(float2*)(C + (long long)(r0 + 8) * ldc + c0) = v;
            }
        }
    }
}

// ---------------------------------------------------------------------------
// rmsnorm over QL=1536 (g_qa -> g_qn)
// ---------------------------------------------------------------------------
__global__ void rmsnorm_q_kernel(const float* __restrict__ w)
{
    const int t = blockIdx.x;
    const float* x = g_qa + (size_t)t * 1536;
    float* y = g_qn + (size_t)t * 1536;
    float v[6];
    float ss = 0.f;
#pragma unroll
    for (int i = 0; i < 6; ++i) {
        v[i] = x[threadIdx.x + i * 256];
        ss += v[i] * v[i];
    }
    __shared__ float sh[8];
    __shared__ float bc;
    for (int o = 16; o; o >>= 1) ss += __shfl_xor_sync(0xffffffffu, ss, o);
    if ((threadIdx.x & 31) == 0) sh[threadIdx.x >> 5] = ss;
    __syncthreads();
    if (threadIdx.x == 0) {
        float s2 = 0.f;
#pragma unroll
        for (int i = 0; i < 8; ++i) s2 += sh[i];
        bc = rsqrtf(s2 * (1.f / 1536.f) + 1e-6f);
    }
    __syncthreads();
    const float inv = bc;
#pragma unroll
    for (int i = 0; i < 6; ++i) {
        int j = threadIdx.x + i * 256;
        y[j] = w[j] * v[i] * inv;
    }
}

// ---------------------------------------------------------------------------
// kv prep: rmsnorm first 512 of g_kvf -> g_kc[:, :512] and g_kvT (transposed);
// rope last 64 -> g_kc[:, 512:576]
// ---------------------------------------------------------------------------
__global__ void kv_prep_kernel(const float* __restrict__ w)
{
    const int t = blockIdx.x;
    const int b = t >> 11, s = t & 2047;
    const float* x = g_kvf + (size_t)t * 576;
    const int j0 = threadIdx.x, j1 = threadIdx.x + 256;
    float v0 = x[j0], v1 = x[j1];
    float ss = v0 * v0 + v1 * v1;
    __shared__ float sh[8];
    __shared__ float bc;
    for (int o = 16; o; o >>= 1) ss += __shfl_xor_sync(0xffffffffu, ss, o);
    if ((threadIdx.x & 31) == 0) sh[threadIdx.x >> 5] = ss;
    __syncthreads();
    if (threadIdx.x == 0) {
        float s2 = 0.f;
#pragma unroll
        for (int i = 0; i < 8; ++i) s2 += sh[i];
        bc = rsqrtf(s2 * (1.f / 512.f) + 1e-6f);
    }
    __syncthreads();
    const float inv = bc;
    float* kc = g_kc + (size_t)t * 576;
    float a0 = w[j0] * v0 * inv;
    float a1 = w[j1] * v1 * inv;
    kc[j0] = a0;
    kc[j1] = a1;
    g_kvT[((size_t)b * 512 + j0) * 2048 + s] = a0;
    g_kvT[((size_t)b * 512 + j1) * 2048 + s] = a1;
    if (threadIdx.x < 32) {
        int i = threadIdx.x;
        float p1 = x[512 + i], p2 = x[544 + i];
        float th = (float)s * expf(-(float)i * ROPE_LF);
        float sn, cs;
        sincosf(th, &sn, &cs);
        kc[512 + i] = p1 * cs - p2 * sn;
        kc[544 + i] = p2 * cs + p1 * sn;
    }
}

// ---------------------------------------------------------------------------
// rope q_pe + scale, packed into g_qc[:, 512:576]
// ---------------------------------------------------------------------------
__global__ void qpe_pack_kernel()
{
    const int idx = blockIdx.x * 256 + threadIdx.x;
    const int i = idx & 31;
    const int h = (idx >> 5) & 15;
    const int t = idx >> 9;
    const int b = t >> 11, s = t & 2047;
    const float* qp = g_q + (size_t)t * 3072 + h * 192 + 128;
    float p1 = qp[i], p2 = qp[32 + i];
    float th = (float)s * expf(-(float)i * ROPE_LF);
    float sn, cs;
    sincosf(th, &sn, &cs);
    float* dst = g_qc + ((size_t)((b * 16 + h) * 2048 + s)) * 576 + 512;
    dst[i]      = (p1 * cs - p2 * sn) * SCALE_QK;
    dst[32 + i] = (p2 * cs + p1 * sn) * SCALE_QK;
}

// ---------------------------------------------------------------------------
// wkv_b[:, :128, :] -> g_wbt[h][c][d]
// ---------------------------------------------------------------------------
__global__ void wbt_kernel(const float* __restrict__ w)
{
    const int idx = blockIdx.x * 256 + threadIdx.x;
    const int d = idx & 127;
    const int c = (idx >> 7) & 511;
    const int h = idx >> 16;
    g_wbt[idx] = w[((size_t)(h * 256 + d)) * 512 + c];
}

// ---------------------------------------------------------------------------
// causal softmax over scores rows (in place). 65536 rows of length s+1.
// Zero-fills (s, next 128-boundary) so the K-clamped 128-tile attn@V GEMM
// reads valid zeros.
// ---------------------------------------------------------------------------
__global__ void softmax_kernel(const int* __restrict__ mask)
{
    const int rid = blockIdx.x;
    const int s = rid & 2047;
    const int b = rid >> 15;               // rid / (16*2048)
    float* row = g_sc + (size_t)rid * 2048;
    const int* mrow = mask + b * 2048;
    const int n = s + 1;
    const int tid = threadIdx.x;

    float x[8];
    float mx = -3.0e38f;
#pragma unroll
    for (int it = 0; it < 8; ++it) {
        int t = tid + it * 256;
        float v = -3.0e38f;
        if (t < n) v = row[t] + (mrow[t] == 0 ? -1e15f : 0.f);
        x[it] = v;
        mx = fmaxf(mx, v);
    }
    __shared__ float sh[8];
    __shared__ float bc;
    for (int o = 16; o; o >>= 1) mx = fmaxf(mx, __shfl_xor_sync(0xffffffffu, mx, o));
    if ((tid & 31) == 0) sh[tid >> 5] = mx;
    __syncthreads();
    if (tid == 0) {
        float m = sh[0];
#pragma unroll
        for (int i = 1; i < 8; ++i) m = fmaxf(m, sh[i]);
        bc = m;
    }
    __syncthreads();
    mx = bc;
    float sum = 0.f;
#pragma unroll
    for (int it = 0; it < 8; ++it) {
        x[it] = expf(x[it] - mx);
        sum += x[it];
    }
    for (int o = 16; o; o >>= 1) sum += __shfl_xor_sync(0xffffffffu, sum, o);
    if ((tid & 31) == 0) sh[tid >> 5] = sum;
    __syncthreads();
    if (tid == 0) {
        float s2 = 0.f;
#pragma unroll
        for (int i = 0; i < 8; ++i) s2 += sh[i];
        bc = 1.f / s2;
    }
    __syncthreads();
    const float rinv = bc;
    const int tend = (s & ~127) + 128;     // 128-tile boundary zero-fill
#pragma unroll
    for (int it = 0; it < 8; ++it) {
        int t = tid + it * 256;
        if (t < n)            row[t] = x[it] * rinv;
        else if (t < tend)    row[t] = 0.f;
    }
}

// ---------------------------------------------------------------------------
// launch
// ---------------------------------------------------------------------------
extern "C" void kernel_launch(void* const* d_in, const int* in_sizes, int n_in,
                              void* d_out, int out_size)
{
    (void)in_sizes; (void)n_in; (void)out_size;
    const float* x        = (const float*)d_in[0];
    const int*   mask     = (const int*)  d_in[1];
    const float* wq_a_w   = (const float*)d_in[2];
    const float* wq_a_b   = (const float*)d_in[3];
    const float* q_norm_w = (const float*)d_in[4];
    const float* wq_b_w   = (const float*)d_in[5];
    const float* wq_b_b   = (const float*)d_in[6];
    const float* wkv_a_w  = (const float*)d_in[7];
    const float* wkv_a_b  = (const float*)d_in[8];
    const float* kv_norm_w= (const float*)d_in[9];
    const float* wkv_b_w  = (const float*)d_in[10];
    const float* wo_w     = (const float*)d_in[11];
    const float* wo_b     = (const float*)d_in[12];
    float* out = (float*)d_out;

    float *qa, *qn, *q, *kvf, *kc, *kvT, *wbt, *qc, *sc, *ol, *oh;
    cudaGetSymbolAddress((void**)&qa,  g_qa);
    cudaGetSymbolAddress((void**)&qn,  g_qn);
    cudaGetSymbolAddress((void**)&q,   g_q);
    cudaGetSymbolAddress((void**)&kvf, g_kvf);
    cudaGetSymbolAddress((void**)&kc,  g_kc);
    cudaGetSymbolAddress((void**)&kvT, g_kvT);
    cudaGetSymbolAddress((void**)&wbt, g_wbt);
    cudaGetSymbolAddress((void**)&qc,  g_qc);
    cudaGetSymbolAddress((void**)&sc,  g_sc);
    cudaGetSymbolAddress((void**)&ol,  g_ol);
    cudaGetSymbolAddress((void**)&oh,  g_oh);

    const dim3 blk(256);

    // q_a = x @ wq_a^T + b                         [4096,1536]
    gemm_tf32<<<dim3(12, 32, 1), blk>>>(x, 2048, 0, 0, wq_a_w, 2048, 0, 0,
                                        qa, 1536, 0, 0, 1536, 2048, wq_a_b, 1.f, 0);
    // rmsnorm
    rmsnorm_q_kernel<<<4096, 256>>>(q_norm_w);
    // q = qn @ wq_b^T + b                          [4096,3072]
    gemm_tf32<<<dim3(24, 32, 1), blk>>>(qn, 1536, 0, 0, wq_b_w, 1536, 0, 0,
                                        q, 3072, 0, 0, 3072, 1536, wq_b_b, 1.f, 0);
    // kv_full = x @ wkv_a^T + b                    [4096,576]  (ragged N)
    gemm_tf32<<<dim3(5, 32, 1), blk>>>(x, 2048, 0, 0, wkv_a_w, 2048, 0, 0,
                                       kvf, 576, 0, 0, 576, 2048, wkv_a_b, 1.f, 0);
    // kv rmsnorm + k_pe rope -> kc, kvT
    kv_prep_kernel<<<4096, 256>>>(kv_norm_w);
    // wkv_b nope-transpose
    wbt_kernel<<<4096, 256>>>(wkv_b_w);
    // q_pe rope + scale into qc[:,512:576]
    qpe_pack_kernel<<<8192, 256>>>();
    // q_lat = q_nope @ wkv_b[:, :128]^T  (scaled)  -> qc[:, :512]
    gemm_tf32<<<dim3(4, 16, 32), blk>>>(
        q, 3072, (long long)2048 * 3072, 192,
        wbt, 128, 0, (long long)512 * 128,
        qc, 576, (long long)16 * 2048 * 576, (long long)2048 * 576,
        512, 128, nullptr, SCALE_QK, 0);
    // scores = Qc @ Kc^T  (causal tile skip)
    gemm_tf32<<<dim3(16, 16, 32), blk>>>(
        qc, 576, (long long)16 * 2048 * 576, (long long)2048 * 576,
        kc, 576, (long long)2048 * 576, 0,
        sc, 2048, (long long)16 * 2048 * 2048, (long long)2048 * 2048,
        2048, 576, nullptr, 1.f, 1);
    // softmax (causal + mask)
    softmax_kernel<<<65536, 256>>>(mask);
    // out_lat = P @ V  (K clamped per 128-row query tile)
    gemm_tf32<<<dim3(4, 16, 32), blk>>>(
        sc, 2048, (long long)16 * 2048 * 2048, (long long)2048 * 2048,
        kvT, 2048, (long long)512 * 2048, 0,
        ol, 512, (long long)16 * 2048 * 512, (long long)2048 * 512,
        512, 2048, nullptr, 1.f, 2);
    // out_head[t, h*128+d] = out_lat @ wkv_b[:, 128:]^T
    gemm_tf32<<<dim3(1, 16, 32), blk>>>(
        ol, 512, (long long)16 * 2048 * 512, (long long)2048 * 512,
        wkv_b_w + 128 * 512, 512, 0, (long long)256 * 512,
        oh, 2048, (long long)2048 * 2048, 128,
        128, 512, nullptr, 1.f, 0);
    // out = out_head @ wo^T + b
    gemm_tf32<<<dim3(16, 32, 1), blk>>>(oh, 2048, 0, 0, wo_w, 2048, 0, 0,
                                        out, 2048, 0, 0, 2048, 2048, wo_b, 1.f, 0);
}

// round 9
// speedup vs baseline: 3.0245x; 1.2257x over previous
#include <cuda_runtime.h>
#include <cuda_bf16.h>
#include <math.h>

// ---------------------------------------------------------------------------
// Problem constants
//   B=2, S=2048, H=2048, NH=16, QL=1536, KVL=512, NOPE=128, ROPE=64, VD=128
//   QKH=192, scale = 1/sqrt(192)
// ---------------------------------------------------------------------------
#define SCALE_QK 0.07216878364870323f
#define ROPE_LF  0.28782313662425574f   /* ln(10000)/32 */

// ---------------------------------------------------------------------------
// Device scratch (static globals — no runtime allocation)
// ---------------------------------------------------------------------------
__device__ float g_qa [(size_t)4096 * 1536];          // x @ wq_a^T + b
__device__ float g_qn [(size_t)4096 * 1536];          // rmsnorm(qa)
__device__ float g_q  [(size_t)4096 * 3072];          // qn @ wq_b^T + b
__device__ float g_kvf[(size_t)4096 * 576];           // x @ wkv_a^T + b
__device__ float g_kc [(size_t)4096 * 576];           // [norm(kv) | rope(k_pe)]
__device__ float g_kvT[(size_t)2 * 512 * 2048];       // per-batch V^T
__device__ float g_wbt[(size_t)16 * 512 * 128];       // wkv_b[:, :128] -> [h][c][d]
__device__ float g_qc [(size_t)32 * 2048 * 576];      // scaled [q_lat | rope(q_pe)]
__device__ float g_sc [(size_t)32 * 2048 * 2048];     // scores / probs
__device__ float g_ol [(size_t)32 * 2048 * 512];      // attn @ V
__device__ float g_oh [(size_t)4096 * 2048];          // per-head out, concat

// ---------------------------------------------------------------------------
// TF32 helpers
// ---------------------------------------------------------------------------
__device__ __forceinline__ unsigned f2tf32(float x) {
    unsigned r;
    asm("cvt.rna.tf32.f32 %0, %1;" : "=r"(r) : "f"(x));
    return r;
}
__device__ __forceinline__ float4 cvt4(float4 v) {
    v.x = __uint_as_float(f2tf32(v.x));
    v.y = __uint_as_float(f2tf32(v.y));
    v.z = __uint_as_float(f2tf32(v.z));
    v.w = __uint_as_float(f2tf32(v.w));
    return v;
}
// select component jj of a float4 (2 SELs)
__device__ __forceinline__ float pick4(float4 v, int jj) {
    float a = (jj & 1) ? v.y : v.x;
    float b = (jj & 1) ? v.w : v.z;
    return (jj & 2) ? b : a;
}
// Stage 4 values of one k-chunk into fragment-layout smem.
// Placement: dst[jj*stride] = v[jj] (fixed); issue order rotated by `rot`
// per-thread so warp-wide STS spread across 16 banks (2-way instead of 8-way).
__device__ __forceinline__ void stage4(float* dst, float4 v, int rot, int stride) {
#pragma unroll
    for (int t = 0; t < 4; ++t) {
        int jj = (t + rot) & 3;
        dst[jj * stride] = pick4(v, jj);
    }
}

// ---------------------------------------------------------------------------
// TF32 tensor-core NT GEMM:  C[m,n] = alpha * sum_k A[m,k]*B[n,k] (+ bias[n])
// A,B row-major K-contiguous. CTA tile 128x128, BK=16, 256 threads
// (8 warps, 2x4 grid of 64x32 warp tiles), mma.m16n8k8.tf32, double-buffered.
// Smem tiles are stored in MMA-FRAGMENT-LINEAR layout:
//   A: frag(kb*8+mb)*128 + lane*4 + reg   -> one LDS.128 per m16k8 fragment
//   B: frag(kb*16+nb)*64 + lane*2 + reg   -> one LDS.64  per k8n8 fragment
// Requires: M % 128 == 0, K % 16 == 0 (all true here). N may be ragged.
// flags bit0: causal tile skip (skip when bn0 >= bm0+128)
// flags bit1: K clamped to min(K, bm0+128)  (attn@V causal K clamp)
// ---------------------------------------------------------------------------
#define BM 128
#define BN 128
#define BK 16

__global__ void __launch_bounds__(256, 2)
gemm_tf32(const float* __restrict__ A, int lda, long long sAb, long long sAh,
          const float* __restrict__ B, int ldb, long long sBb, long long sBh,
          float* __restrict__ C, int ldc, long long sCb, long long sCh,
          int N, int K, const float* __restrict__ bias, float alpha, int flags)
{
    const long long zb = blockIdx.z >> 4;
    const long long zh = blockIdx.z & 15;
    const int bm0 = blockIdx.y * BM;
    const int bn0 = blockIdx.x * BN;
    if ((flags & 1) && bn0 >= bm0 + BM) return;
    const int Kl = (flags & 2) ? min(K, bm0 + BM) : K;

    A += zb * sAb + zh * sAh + (long long)bm0 * lda;
    B += zb * sBb + zh * sBh + (long long)bn0 * ldb;
    C += zb * sCb + zh * sCh;

    __shared__ float As[2 * 2048];
    __shared__ float Bs[2 * 2048];

    const int tid  = threadIdx.x;
    const int lane = tid & 31;
    const int warp = tid >> 5;
    const int wm   = warp >> 2;        // 0..1
    const int wn   = warp & 3;         // 0..3
    const int lq   = lane >> 2;        // 0..7
    const int lr   = lane & 3;         // 0..3

    // ---- staging-side indices ----
    const int lm     = tid >> 2;       // 0..63 : tile row this thread loads
    const int lm_off = lm & 7;
    const int lk     = (tid & 3) * 4;  // 0,4,8,12
    const int kb_w   = lk >> 3;        // k8-block
    const int kbit   = (lk >> 2) & 1;  // reg bit from k
    const int rbit   = (lm >> 3) & 1;  // reg bit from row (same for lm, lm+64)
    const int lane0  = lm_off * 4;
    const int rotA   = lm_off >> 1;
    const int rotB   = lm_off >> 2;

    const int mb0    = lm >> 4;                                  // 0..3
    const int baseA0 = (kb_w * 8 + mb0) * 128 + lane0 * 4 + rbit + 2 * kbit;
    const int baseA1 = baseA0 + 4 * 128;                         // mb + 4
    const int nb0    = lm >> 3;                                  // 0..7
    const int baseB0 = (kb_w * 16 + nb0) * 64 + lane0 * 2 + kbit;
    const int baseB1 = baseB0 + 8 * 64;                          // nb + 8

    // ---- consumer-side indices ----
    const int rdA = lane * 4;
    const int rdB = lane * 2;

    const float* Ag0 = A + (long long)lm * lda + lk;
    const float* Ag1 = Ag0 + (long long)64 * lda;
    const bool bv0 = (bn0 + lm)      < N;
    const bool bv1 = (bn0 + lm + 64) < N;
    const float* Bg0 = B + (long long)lm * ldb + lk;
    const float* Bg1 = Bg0 + (long long)64 * ldb;

    float acc[4][4][4];
#pragma unroll
    for (int i = 0; i < 4; ++i)
#pragma unroll
        for (int j = 0; j < 4; ++j)
#pragma unroll
            for (int r = 0; r < 4; ++r) acc[i][j][r] = 0.f;

    const int nK = Kl / BK;
    const float4 z4 = make_float4(0.f, 0.f, 0.f, 0.f);

    float4 ra0 = *(const float4*)(Ag0);
    float4 ra1 = *(const float4*)(Ag1);
    float4 rb0 = bv0 ? *(const float4*)(Bg0) : z4;
    float4 rb1 = bv1 ? *(const float4*)(Bg1) : z4;

    // stage 0
    stage4(&As[baseA0], cvt4(ra0), rotA, 4);
    stage4(&As[baseA1], cvt4(ra1), rotA, 4);
    stage4(&Bs[baseB0], cvt4(rb0), rotB, 2);
    stage4(&Bs[baseB1], cvt4(rb1), rotB, 2);
    __syncthreads();

    for (int kt = 0; kt < nK; ++kt) {
        const int sb = (kt & 1) * 2048;
        if (kt + 1 < nK) {
            const int k0 = (kt + 1) * BK;
            ra0 = *(const float4*)(Ag0 + k0);
            ra1 = *(const float4*)(Ag1 + k0);
            rb0 = bv0 ? *(const float4*)(Bg0 + k0) : z4;
            rb1 = bv1 ? *(const float4*)(Bg1 + k0) : z4;
        }
#pragma unroll
        for (int kb = 0; kb < 2; ++kb) {
            float2 b2[4];
            float4 a4[4];
#pragma unroll
            for (int ni = 0; ni < 4; ++ni)
                b2[ni] = *(const float2*)&Bs[sb + (kb * 16 + wn * 4 + ni) * 64 + rdB];
#pragma unroll
            for (int mi = 0; mi < 4; ++mi)
                a4[mi] = *(const float4*)&As[sb + (kb * 8 + wm * 4 + mi) * 128 + rdA];
#pragma unroll
            for (int mi = 0; mi < 4; ++mi)
#pragma unroll
                for (int ni = 0; ni < 4; ++ni) {
                    asm volatile(
                        "mma.sync.aligned.m16n8k8.row.col.f32.tf32.tf32.f32 "
                        "{%0,%1,%2,%3}, {%4,%5,%6,%7}, {%8,%9}, {%0,%1,%2,%3};\n"
                        : "+f"(acc[mi][ni][0]), "+f"(acc[mi][ni][1]),
                          "+f"(acc[mi][ni][2]), "+f"(acc[mi][ni][3])
                        : "r"(__float_as_uint(a4[mi].x)), "r"(__float_as_uint(a4[mi].y)),
                          "r"(__float_as_uint(a4[mi].z)), "r"(__float_as_uint(a4[mi].w)),
                          "r"(__float_as_uint(b2[ni].x)), "r"(__float_as_uint(b2[ni].y)));
                }
        }
        if (kt + 1 < nK) {
            const int nb = ((kt + 1) & 1) * 2048;
            stage4(&As[nb + baseA0], cvt4(ra0), rotA, 4);
            stage4(&As[nb + baseA1], cvt4(ra1), rotA, 4);
            stage4(&Bs[nb + baseB0], cvt4(rb0), rotB, 2);
            stage4(&Bs[nb + baseB1], cvt4(rb1), rotB, 2);
        }
        __syncthreads();
    }

    // epilogue
#pragma unroll
    for (int mi = 0; mi < 4; ++mi) {
        const int r0 = bm0 + wm * 64 + mi * 16 + lq;
#pragma unroll
        for (int ni = 0; ni < 4; ++ni) {
            const int c0 = bn0 + wn * 32 + ni * 8 + 2 * lr;
            if (c0 < N) {
                float b0 = 0.f, b1 = 0.f;
                if (bias) { b0 = bias[c0]; b1 = bias[c0 + 1]; }
                float2 v;
                v.x = alpha * acc[mi][ni][0] + b0;
                v.y = alpha * acc[mi][ni][1] + b1;
                *(float2*)(C + (long long)r0 * ldc + c0) = v;
                v.x = alpha * acc[mi][ni][2] + b0;
                v.y = alpha * acc[mi][ni][3] + b1;
                *(float2*)(C + (long long)(r0 + 8) * ldc + c0) = v;
            }
        }
    }
}

// ---------------------------------------------------------------------------
// rmsnorm over QL=1536 (g_qa -> g_qn)
// ---------------------------------------------------------------------------
__global__ void rmsnorm_q_kernel(const float* __restrict__ w)
{
    const int t = blockIdx.x;
    const float* x = g_qa + (size_t)t * 1536;
    float* y = g_qn + (size_t)t * 1536;
    float v[6];
    float ss = 0.f;
#pragma unroll
    for (int i = 0; i < 6; ++i) {
        v[i] = x[threadIdx.x + i * 256];
        ss += v[i] * v[i];
    }
    __shared__ float sh[8];
    __shared__ float bc;
    for (int o = 16; o; o >>= 1) ss += __shfl_xor_sync(0xffffffffu, ss, o);
    if ((threadIdx.x & 31) == 0) sh[threadIdx.x >> 5] = ss;
    __syncthreads();
    if (threadIdx.x == 0) {
        float s2 = 0.f;
#pragma unroll
        for (int i = 0; i < 8; ++i) s2 += sh[i];
        bc = rsqrtf(s2 * (1.f / 1536.f) + 1e-6f);
    }
    __syncthreads();
    const float inv = bc;
#pragma unroll
    for (int i = 0; i < 6; ++i) {
        int j = threadIdx.x + i * 256;
        y[j] = w[j] * v[i] * inv;
    }
}

// ---------------------------------------------------------------------------
// kv prep: rmsnorm first 512 of g_kvf -> g_kc[:, :512] and g_kvT (transposed);
// rope last 64 -> g_kc[:, 512:576]
// ---------------------------------------------------------------------------
__global__ void kv_prep_kernel(const float* __restrict__ w)
{
    const int t = blockIdx.x;
    const int b = t >> 11, s = t & 2047;
    const float* x = g_kvf + (size_t)t * 576;
    const int j0 = threadIdx.x, j1 = threadIdx.x + 256;
    float v0 = x[j0], v1 = x[j1];
    float ss = v0 * v0 + v1 * v1;
    __shared__ float sh[8];
    __shared__ float bc;
    for (int o = 16; o; o >>= 1) ss += __shfl_xor_sync(0xffffffffu, ss, o);
    if ((threadIdx.x & 31) == 0) sh[threadIdx.x >> 5] = ss;
    __syncthreads();
    if (threadIdx.x == 0) {
        float s2 = 0.f;
#pragma unroll
        for (int i = 0; i < 8; ++i) s2 += sh[i];
        bc = rsqrtf(s2 * (1.f / 512.f) + 1e-6f);
    }
    __syncthreads();
    const float inv = bc;
    float* kc = g_kc + (size_t)t * 576;
    float a0 = w[j0] * v0 * inv;
    float a1 = w[j1] * v1 * inv;
    kc[j0] = a0;
    kc[j1] = a1;
    g_kvT[((size_t)b * 512 + j0) * 2048 + s] = a0;
    g_kvT[((size_t)b * 512 + j1) * 2048 + s] = a1;
    if (threadIdx.x < 32) {
        int i = threadIdx.x;
        float p1 = x[512 + i], p2 = x[544 + i];
        float th = (float)s * expf(-(float)i * ROPE_LF);
        float sn, cs;
        sincosf(th, &sn, &cs);
        kc[512 + i] = p1 * cs - p2 * sn;
        kc[544 + i] = p2 * cs + p1 * sn;
    }
}

// ---------------------------------------------------------------------------
// rope q_pe + scale, packed into g_qc[:, 512:576]
// ---------------------------------------------------------------------------
__global__ void qpe_pack_kernel()
{
    const int idx = blockIdx.x * 256 + threadIdx.x;
    const int i = idx & 31;
    const int h = (idx >> 5) & 15;
    const int t = idx >> 9;
    const int b = t >> 11, s = t & 2047;
    const float* qp = g_q + (size_t)t * 3072 + h * 192 + 128;
    float p1 = qp[i], p2 = qp[32 + i];
    float th = (float)s * expf(-(float)i * ROPE_LF);
    float sn, cs;
    sincosf(th, &sn, &cs);
    float* dst = g_qc + ((size_t)((b * 16 + h) * 2048 + s)) * 576 + 512;
    dst[i]      = (p1 * cs - p2 * sn) * SCALE_QK;
    dst[32 + i] = (p2 * cs + p1 * sn) * SCALE_QK;
}

// ---------------------------------------------------------------------------
// wkv_b[:, :128, :] -> g_wbt[h][c][d]
// ---------------------------------------------------------------------------
__global__ void wbt_kernel(const float* __restrict__ w)
{
    const int idx = blockIdx.x * 256 + threadIdx.x;
    const int d = idx & 127;
    const int c = (idx >> 7) & 511;
    const int h = idx >> 16;
    g_wbt[idx] = w[((size_t)(h * 256 + d)) * 512 + c];
}

// ---------------------------------------------------------------------------
// causal softmax over scores rows (in place). 65536 rows of length s+1.
// Zero-fills (s, next 128-boundary) so the K-clamped 128-tile attn@V GEMM
// reads valid zeros.
// ---------------------------------------------------------------------------
__global__ void softmax_kernel(const int* __restrict__ mask)
{
    const int rid = blockIdx.x;
    const int s = rid & 2047;
    const int b = rid >> 15;               // rid / (16*2048)
    float* row = g_sc + (size_t)rid * 2048;
    const int* mrow = mask + b * 2048;
    const int n = s + 1;
    const int tid = threadIdx.x;

    float x[8];
    float mx = -3.0e38f;
#pragma unroll
    for (int it = 0; it < 8; ++it) {
        int t = tid + it * 256;
        float v = -3.0e38f;
        if (t < n) v = row[t] + (mrow[t] == 0 ? -1e15f : 0.f);
        x[it] = v;
        mx = fmaxf(mx, v);
    }
    __shared__ float sh[8];
    __shared__ float bc;
    for (int o = 16; o; o >>= 1) mx = fmaxf(mx, __shfl_xor_sync(0xffffffffu, mx, o));
    if ((tid & 31) == 0) sh[tid >> 5] = mx;
    __syncthreads();
    if (tid == 0) {
        float m = sh[0];
#pragma unroll
        for (int i = 1; i < 8; ++i) m = fmaxf(m, sh[i]);
        bc = m;
    }
    __syncthreads();
    mx = bc;
    float sum = 0.f;
#pragma unroll
    for (int it = 0; it < 8; ++it) {
        x[it] = expf(x[it] - mx);
        sum += x[it];
    }
    for (int o = 16; o; o >>= 1) sum += __shfl_xor_sync(0xffffffffu, sum, o);
    if ((tid & 31) == 0) sh[tid >> 5] = sum;
    __syncthreads();
    if (tid == 0) {
        float s2 = 0.f;
#pragma unroll
        for (int i = 0; i < 8; ++i) s2 += sh[i];
        bc = 1.f / s2;
    }
    __syncthreads();
    const float rinv = bc;
    const int tend = (s & ~127) + 128;     // 128-tile boundary zero-fill
#pragma unroll
    for (int it = 0; it < 8; ++it) {
        int t = tid + it * 256;
        if (t < n)            row[t] = x[it] * rinv;
        else if (t < tend)    row[t] = 0.f;
    }
}

// ---------------------------------------------------------------------------
// launch
// ---------------------------------------------------------------------------
extern "C" void kernel_launch(void* const* d_in, const int* in_sizes, int n_in,
                              void* d_out, int out_size)
{
    (void)in_sizes; (void)n_in; (void)out_size;
    const float* x        = (const float*)d_in[0];
    const int*   mask     = (const int*)  d_in[1];
    const float* wq_a_w   = (const float*)d_in[2];
    const float* wq_a_b   = (const float*)d_in[3];
    const float* q_norm_w = (const float*)d_in[4];
    const float* wq_b_w   = (const float*)d_in[5];
    const float* wq_b_b   = (const float*)d_in[6];
    const float* wkv_a_w  = (const float*)d_in[7];
    const float* wkv_a_b  = (const float*)d_in[8];
    const float* kv_norm_w= (const float*)d_in[9];
    const float* wkv_b_w  = (const float*)d_in[10];
    const float* wo_w     = (const float*)d_in[11];
    const float* wo_b     = (const float*)d_in[12];
    float* out = (float*)d_out;

    float *qa, *qn, *q, *kvf, *kc, *kvT, *wbt, *qc, *sc, *ol, *oh;
    cudaGetSymbolAddress((void**)&qa,  g_qa);
    cudaGetSymbolAddress((void**)&qn,  g_qn);
    cudaGetSymbolAddress((void**)&q,   g_q);
    cudaGetSymbolAddress((void**)&kvf, g_kvf);
    cudaGetSymbolAddress((void**)&kc,  g_kc);
    cudaGetSymbolAddress((void**)&kvT, g_kvT);
    cudaGetSymbolAddress((void**)&wbt, g_wbt);
    cudaGetSymbolAddress((void**)&qc,  g_qc);
    cudaGetSymbolAddress((void**)&sc,  g_sc);
    cudaGetSymbolAddress((void**)&ol,  g_ol);
    cudaGetSymbolAddress((void**)&oh,  g_oh);

    const dim3 blk(256);

    // q_a = x @ wq_a^T + b                         [4096,1536]
    gemm_tf32<<<dim3(12, 32, 1), blk>>>(x, 2048, 0, 0, wq_a_w, 2048, 0, 0,
                                        qa, 1536, 0, 0, 1536, 2048, wq_a_b, 1.f, 0);
    // rmsnorm
    rmsnorm_q_kernel<<<4096, 256>>>(q_norm_w);
    // q = qn @ wq_b^T + b                          [4096,3072]
    gemm_tf32<<<dim3(24, 32, 1), blk>>>(qn, 1536, 0, 0, wq_b_w, 1536, 0, 0,
                                        q, 3072, 0, 0, 3072, 1536, wq_b_b, 1.f, 0);
    // kv_full = x @ wkv_a^T + b                    [4096,576]  (ragged N)
    gemm_tf32<<<dim3(5, 32, 1), blk>>>(x, 2048, 0, 0, wkv_a_w, 2048, 0, 0,
                                       kvf, 576, 0, 0, 576, 2048, wkv_a_b, 1.f, 0);
    // kv rmsnorm + k_pe rope -> kc, kvT
    kv_prep_kernel<<<4096, 256>>>(kv_norm_w);
    // wkv_b nope-transpose
    wbt_kernel<<<4096, 256>>>(wkv_b_w);
    // q_pe rope + scale into qc[:,512:576]
    qpe_pack_kernel<<<8192, 256>>>();
    // q_lat = q_nope @ wkv_b[:, :128]^T  (scaled)  -> qc[:, :512]
    gemm_tf32<<<dim3(4, 16, 32), blk>>>(
        q, 3072, (long long)2048 * 3072, 192,
        wbt, 128, 0, (long long)512 * 128,
        qc, 576, (long long)16 * 2048 * 576, (long long)2048 * 576,
        512, 128, nullptr, SCALE_QK, 0);
    // scores = Qc @ Kc^T  (causal tile skip)
    gemm_tf32<<<dim3(16, 16, 32), blk>>>(
        qc, 576, (long long)16 * 2048 * 576, (long long)2048 * 576,
        kc, 576, (long long)2048 * 576, 0,
        sc, 2048, (long long)16 * 2048 * 2048, (long long)2048 * 2048,
        2048, 576, nullptr, 1.f, 1);
    // softmax (causal + mask)
    softmax_kernel<<<65536, 256>>>(mask);
    // out_lat = P @ V  (K clamped per 128-row query tile)
    gemm_tf32<<<dim3(4, 16, 32), blk>>>(
        sc, 2048, (long long)16 * 2048 * 2048, (long long)2048 * 2048,
        kvT, 2048, (long long)512 * 2048, 0,
        ol, 512, (long long)16 * 2048 * 512, (long long)2048 * 512,
        512, 2048, nullptr, 1.f, 2);
    // out_head[t, h*128+d] = out_lat @ wkv_b[:, 128:]^T
    gemm_tf32<<<dim3(1, 16, 32), blk>>>(
        ol, 512, (long long)16 * 2048 * 512, (long long)2048 * 512,
        wkv_b_w + 128 * 512, 512, 0, (long long)256 * 512,
        oh, 2048, (long long)2048 * 2048, 128,
        128, 512, nullptr, 1.f, 0);
    // out = out_head @ wo^T + b
    gemm_tf32<<<dim3(16, 32, 1), blk>>>(oh, 2048, 0, 0, wo_w, 2048, 0, 0,
                                        out, 2048, 0, 0, 2048, 2048, wo_b, 1.f, 0);
}

// round 11
// speedup vs baseline: 3.3486x; 1.1072x over previous
#include <cuda_runtime.h>
#include <cuda_bf16.h>
#include <math.h>

// ---------------------------------------------------------------------------
// Problem constants
//   B=2, S=2048, H=2048, NH=16, QL=1536, KVL=512, NOPE=128, ROPE=64, VD=128
//   QKH=192, scale = 1/sqrt(192)
// ---------------------------------------------------------------------------
#define SCALE_QK 0.07216878364870323f
#define ROPE_LF  0.28782313662425574f   /* ln(10000)/32 */

// ---------------------------------------------------------------------------
// Device scratch (static globals — no runtime allocation)
// ---------------------------------------------------------------------------
__device__ float g_qa [(size_t)4096 * 1536];          // x @ wq_a^T + b
__device__ float g_qn [(size_t)4096 * 1536];          // rmsnorm(qa)
__device__ float g_q  [(size_t)4096 * 3072];          // qn @ wq_b^T + b
__device__ float g_kvf[(size_t)4096 * 576];           // x @ wkv_a^T + b
__device__ float g_kc [(size_t)4096 * 576];           // [norm(kv) | rope(k_pe)]
__device__ float g_kvT[(size_t)2 * 512 * 2048];       // per-batch V^T
__device__ float g_wbt[(size_t)16 * 512 * 128];       // wkv_b[:, :128] -> [h][c][d]
__device__ float g_qc [(size_t)32 * 2048 * 576];      // scaled [q_lat | rope(q_pe)]
__device__ float g_sc [(size_t)32 * 2048 * 2048];     // scores / probs
__device__ float g_ol [(size_t)32 * 2048 * 512];      // attn @ V
__device__ float g_oh [(size_t)4096 * 2048];          // per-head out, concat

// ---------------------------------------------------------------------------
// TF32 helpers
// ---------------------------------------------------------------------------
__device__ __forceinline__ unsigned f2tf32(float x) {
    unsigned r;
    asm("cvt.rna.tf32.f32 %0, %1;" : "=r"(r) : "f"(x));
    return r;
}
__device__ __forceinline__ float4 cvt4(float4 v) {
    v.x = __uint_as_float(f2tf32(v.x));
    v.y = __uint_as_float(f2tf32(v.y));
    v.z = __uint_as_float(f2tf32(v.z));
    v.w = __uint_as_float(f2tf32(v.w));
    return v;
}
// select component jj of a float4 (2 SELs)
__device__ __forceinline__ float pick4(float4 v, int jj) {
    float a = (jj & 1) ? v.y : v.x;
    float b = (jj & 1) ? v.w : v.z;
    return (jj & 2) ? b : a;
}
// Stage 4 values of one k-chunk into fragment-layout smem.
// Placement: dst[jj*4] = v[jj] (fixed); issue order rotated by `rot`
// per-thread so warp-wide STS spread across banks (2-way instead of 8-way).
__device__ __forceinline__ void stage4(float* dst, float4 v, int rot) {
#pragma unroll
    for (int t = 0; t < 4; ++t) {
        int jj = (t + rot) & 3;
        dst[jj * 4] = pick4(v, jj);
    }
}

// ---------------------------------------------------------------------------
// TF32 tensor-core NT GEMM:  C[m,n] = alpha * sum_k A[m,k]*B[n,k] (+ bias[n])
// A,B row-major K-contiguous. CTA tile 128x128, BK=16, 128 threads
// (4 warps, 2x2 grid of 64x64 warp tiles), mma.m16n8k8.tf32, double-buffered.
// Smem tiles stored in MMA-FRAGMENT-LINEAR layout; both A and B fragments are
// fetched with a single LDS.128 per fragment(-pair):
//   A: frag(kb*8+mb)*128 + lane*4 + (rbit + 2*kbit)
//   B: pair(kb*8+pb)*128 + lane*4 + (2*sub + kbit)   (two n8-frags per LDS.128)
// Requires: M % 128 == 0, K % 16 == 0 (all true here). N may be ragged.
// flags bit0: causal tile skip (skip when bn0 >= bm0+128)
// flags bit1: K clamped to min(K, bm0+128)  (attn@V causal K clamp)
// ---------------------------------------------------------------------------
#define BM 128
#define BN 128
#define BK 16

__global__ void __launch_bounds__(128, 2)
gemm_tf32(const float* __restrict__ A, int lda, long long sAb, long long sAh,
          const float* __restrict__ B, int ldb, long long sBb, long long sBh,
          float* __restrict__ C, int ldc, long long sCb, long long sCh,
          int N, int K, const float* __restrict__ bias, float alpha, int flags)
{
    const long long zb = blockIdx.z >> 4;
    const long long zh = blockIdx.z & 15;
    const int bm0 = blockIdx.y * BM;
    const int bn0 = blockIdx.x * BN;
    if ((flags & 1) && bn0 >= bm0 + BM) return;
    const int Kl = (flags & 2) ? min(K, bm0 + BM) : K;

    A += zb * sAb + zh * sAh + (long long)bm0 * lda;
    B += zb * sBb + zh * sBh + (long long)bn0 * ldb;
    C += zb * sCb + zh * sCh;

    __shared__ float As[2 * 2048];
    __shared__ float Bs[2 * 2048];

    const int tid  = threadIdx.x;
    const int lane = tid & 31;
    const int warp = tid >> 5;         // 0..3
    const int wm   = warp >> 1;        // 0..1
    const int wn   = warp & 1;         // 0..1
    const int lq   = lane >> 2;        // 0..7
    const int lr   = lane & 3;         // 0..3

    // ---- staging-side indices ----
    const int lm   = tid >> 2;         // 0..31 : base tile row this thread loads
    const int lmo  = lm & 7;
    const int lk   = (tid & 3) * 4;    // 0,4,8,12
    const int kb_w = lk >> 3;          // k8-block
    const int kbit = (lk >> 2) & 1;    // reg bit from k
    const int rbit = (lm >> 3) & 1;    // same for lm+32*i
    const int rot  = lmo >> 1;

    // rows lm + 32*i  ->  frag/pair index (lm>>4) + 2*i  ->  +256 floats per i
    const int baseA = (kb_w * 8 + (lm >> 4)) * 128 + lmo * 16 + rbit + 2 * kbit;
    const int baseB = (kb_w * 8 + (lm >> 4)) * 128 + lmo * 16 + 2 * rbit + kbit;

    // ---- consumer-side ----
    const int rd = lane * 4;

    const float* Ag = A + (long long)lm * lda + lk;
    const float* Bg = B + (long long)lm * ldb + lk;
    bool bv[4];
#pragma unroll
    for (int i = 0; i < 4; ++i) bv[i] = (bn0 + lm + 32 * i) < N;

    float acc[4][8][4];
#pragma unroll
    for (int i = 0; i < 4; ++i)
#pragma unroll
        for (int j = 0; j < 8; ++j)
#pragma unroll
            for (int r = 0; r < 4; ++r) acc[i][j][r] = 0.f;

    const int nK = Kl / BK;
    const float4 z4 = make_float4(0.f, 0.f, 0.f, 0.f);

    float4 ra[4], rb[4];
#pragma unroll
    for (int i = 0; i < 4; ++i) {
        ra[i] = *(const float4*)(Ag + (long long)(32 * i) * lda);
        rb[i] = bv[i] ? *(const float4*)(Bg + (long long)(32 * i) * ldb) : z4;
    }
#pragma unroll
    for (int i = 0; i < 4; ++i) {
        stage4(&As[baseA + i * 256], cvt4(ra[i]), rot);
        stage4(&Bs[baseB + i * 256], cvt4(rb[i]), rot);
    }
    __syncthreads();

    for (int kt = 0; kt < nK; ++kt) {
        const int sb = (kt & 1) * 2048;
        if (kt + 1 < nK) {
            const long long k0 = (kt + 1) * BK;
#pragma unroll
            for (int i = 0; i < 4; ++i) {
                ra[i] = *(const float4*)(Ag + (long long)(32 * i) * lda + k0);
                rb[i] = bv[i] ? *(const float4*)(Bg + (long long)(32 * i) * ldb + k0) : z4;
            }
        }
#pragma unroll
        for (int kb = 0; kb < 2; ++kb) {
            float4 a4[4], bp[4];
#pragma unroll
            for (int p = 0; p < 4; ++p)
                bp[p] = *(const float4*)&Bs[sb + (kb * 8 + wn * 4 + p) * 128 + rd];
#pragma unroll
            for (int mi = 0; mi < 4; ++mi)
                a4[mi] = *(const float4*)&As[sb + (kb * 8 + wm * 4 + mi) * 128 + rd];
#pragma unroll
            for (int mi = 0; mi < 4; ++mi)
#pragma unroll
                for (int p = 0; p < 4; ++p) {
                    asm volatile(
                        "mma.sync.aligned.m16n8k8.row.col.f32.tf32.tf32.f32 "
                        "{%0,%1,%2,%3}, {%4,%5,%6,%7}, {%8,%9}, {%0,%1,%2,%3};\n"
                        : "+f"(acc[mi][2 * p][0]), "+f"(acc[mi][2 * p][1]),
                          "+f"(acc[mi][2 * p][2]), "+f"(acc[mi][2 * p][3])
                        : "r"(__float_as_uint(a4[mi].x)), "r"(__float_as_uint(a4[mi].y)),
                          "r"(__float_as_uint(a4[mi].z)), "r"(__float_as_uint(a4[mi].w)),
                          "r"(__float_as_uint(bp[p].x)), "r"(__float_as_uint(bp[p].y)));
                    asm volatile(
                        "mma.sync.aligned.m16n8k8.row.col.f32.tf32.tf32.f32 "
                        "{%0,%1,%2,%3}, {%4,%5,%6,%7}, {%8,%9}, {%0,%1,%2,%3};\n"
                        : "+f"(acc[mi][2 * p + 1][0]), "+f"(acc[mi][2 * p + 1][1]),
                          "+f"(acc[mi][2 * p + 1][2]), "+f"(acc[mi][2 * p + 1][3])
                        : "r"(__float_as_uint(a4[mi].x)), "r"(__float_as_uint(a4[mi].y)),
                          "r"(__float_as_uint(a4[mi].z)), "r"(__float_as_uint(a4[mi].w)),
                          "r"(__float_as_uint(bp[p].z)), "r"(__float_as_uint(bp[p].w)));
                }
        }
        if (kt + 1 < nK) {
            const int nb = ((kt + 1) & 1) * 2048;
#pragma unroll
            for (int i = 0; i < 4; ++i) {
                stage4(&As[nb + baseA + i * 256], cvt4(ra[i]), rot);
                stage4(&Bs[nb + baseB + i * 256], cvt4(rb[i]), rot);
            }
        }
        __syncthreads();
    }

    // epilogue
#pragma unroll
    for (int mi = 0; mi < 4; ++mi) {
        const int r0 = bm0 + wm * 64 + mi * 16 + lq;
#pragma unroll
        for (int ni = 0; ni < 8; ++ni) {
            const int c0 = bn0 + wn * 64 + ni * 8 + 2 * lr;
            if (c0 < N) {
                float b0 = 0.f, b1 = 0.f;
                if (bias) { b0 = bias[c0]; b1 = bias[c0 + 1]; }
                float2 v;
                v.x = alpha * acc[mi][ni][0] + b0;
                v.y = alpha * acc[mi][ni][1] + b1;
                *(float2*)(C + (long long)r0 * ldc + c0) = v;
                v.x = alpha * acc[mi][ni][2] + b0;
                v.y = alpha * acc[mi][ni][3] + b1;
                *(float2*)(C + (long long)(r0 + 8) * ldc + c0) = v;
            }
        }
    }
}

// ---------------------------------------------------------------------------
// rmsnorm over QL=1536 (g_qa -> g_qn)
// ---------------------------------------------------------------------------
__global__ void rmsnorm_q_kernel(const float* __restrict__ w)
{
    const int t = blockIdx.x;
    const float* x = g_qa + (size_t)t * 1536;
    float* y = g_qn + (size_t)t * 1536;
    float v[6];
    float ss = 0.f;
#pragma unroll
    for (int i = 0; i < 6; ++i) {
        v[i] = x[threadIdx.x + i * 256];
        ss += v[i] * v[i];
    }
    __shared__ float sh[8];
    __shared__ float bc;
    for (int o = 16; o; o >>= 1) ss += __shfl_xor_sync(0xffffffffu, ss, o);
    if ((threadIdx.x & 31) == 0) sh[threadIdx.x >> 5] = ss;
    __syncthreads();
    if (threadIdx.x == 0) {
        float s2 = 0.f;
#pragma unroll
        for (int i = 0; i < 8; ++i) s2 += sh[i];
        bc = rsqrtf(s2 * (1.f / 1536.f) + 1e-6f);
    }
    __syncthreads();
    const float inv = bc;
#pragma unroll
    for (int i = 0; i < 6; ++i) {
        int j = threadIdx.x + i * 256;
        y[j] = w[j] * v[i] * inv;
    }
}

// ---------------------------------------------------------------------------
// kv prep: rmsnorm first 512 of g_kvf -> g_kc[:, :512] and g_kvT (transposed);
// rope last 64 -> g_kc[:, 512:576]
// ---------------------------------------------------------------------------
__global__ void kv_prep_kernel(const float* __restrict__ w)
{
    const int t = blockIdx.x;
    const int b = t >> 11, s = t & 2047;
    const float* x = g_kvf + (size_t)t * 576;
    const int j0 = threadIdx.x, j1 = threadIdx.x + 256;
    float v0 = x[j0], v1 = x[j1];
    float ss = v0 * v0 + v1 * v1;
    __shared__ float sh[8];
    __shared__ float bc;
    for (int o = 16; o; o >>= 1) ss += __shfl_xor_sync(0xffffffffu, ss, o);
    if ((threadIdx.x & 31) == 0) sh[threadIdx.x >> 5] = ss;
    __syncthreads();
    if (threadIdx.x == 0) {
        float s2 = 0.f;
#pragma unroll
        for (int i = 0; i < 8; ++i) s2 += sh[i];
        bc = rsqrtf(s2 * (1.f / 512.f) + 1e-6f);
    }
    __syncthreads();
    const float inv = bc;
    float* kc = g_kc + (size_t)t * 576;
    float a0 = w[j0] * v0 * inv;
    float a1 = w[j1] * v1 * inv;
    kc[j0] = a0;
    kc[j1] = a1;
    g_kvT[((size_t)b * 512 + j0) * 2048 + s] = a0;
    g_kvT[((size_t)b * 512 + j1) * 2048 + s] = a1;
    if (threadIdx.x < 32) {
        int i = threadIdx.x;
        float p1 = x[512 + i], p2 = x[544 + i];
        float th = (float)s * expf(-(float)i * ROPE_LF);
        float sn, cs;
        sincosf(th, &sn, &cs);
        kc[512 + i] = p1 * cs - p2 * sn;
        kc[544 + i] = p2 * cs + p1 * sn;
    }
}

// ---------------------------------------------------------------------------
// rope q_pe + scale, packed into g_qc[:, 512:576]
// ---------------------------------------------------------------------------
__global__ void qpe_pack_kernel()
{
    const int idx = blockIdx.x * 256 + threadIdx.x;
    const int i = idx & 31;
    const int h = (idx >> 5) & 15;
    const int t = idx >> 9;
    const int b = t >> 11, s = t & 2047;
    const float* qp = g_q + (size_t)t * 3072 + h * 192 + 128;
    float p1 = qp[i], p2 = qp[32 + i];
    float th = (float)s * expf(-(float)i * ROPE_LF);
    float sn, cs;
    sincosf(th, &sn, &cs);
    float* dst = g_qc + ((size_t)((b * 16 + h) * 2048 + s)) * 576 + 512;
    dst[i]      = (p1 * cs - p2 * sn) * SCALE_QK;
    dst[32 + i] = (p2 * cs + p1 * sn) * SCALE_QK;
}

// ---------------------------------------------------------------------------
// wkv_b[:, :128, :] -> g_wbt[h][c][d]
// ---------------------------------------------------------------------------
__global__ void wbt_kernel(const float* __restrict__ w)
{
    const int idx = blockIdx.x * 256 + threadIdx.x;
    const int d = idx & 127;
    const int c = (idx >> 7) & 511;
    const int h = idx >> 16;
    g_wbt[idx] = w[((size_t)(h * 256 + d)) * 512 + c];
}

// ---------------------------------------------------------------------------
// causal softmax over scores rows (in place). 65536 rows of length s+1.
// Zero-fills (s, next 128-boundary) so the K-clamped 128-tile attn@V GEMM
// reads valid zeros.
// ---------------------------------------------------------------------------
__global__ void softmax_kernel(const int* __restrict__ mask)
{
    const int rid = blockIdx.x;
    const int s = rid & 2047;
    const int b = rid >> 15;               // rid / (16*2048)
    float* row = g_sc + (size_t)rid * 2048;
    const int* mrow = mask + b * 2048;
    const int n = s + 1;
    const int tid = threadIdx.x;

    float x[8];
    float mx = -3.0e38f;
#pragma unroll
    for (int it = 0; it < 8; ++it) {
        int t = tid + it * 256;
        float v = -3.0e38f;
        if (t < n) v = row[t] + (mrow[t] == 0 ? -1e15f : 0.f);
        x[it] = v;
        mx = fmaxf(mx, v);
    }
    __shared__ float sh[8];
    __shared__ float bc;
    for (int o = 16; o; o >>= 1) mx = fmaxf(mx, __shfl_xor_sync(0xffffffffu, mx, o));
    if ((tid & 31) == 0) sh[tid >> 5] = mx;
    __syncthreads();
    if (tid == 0) {
        float m = sh[0];
#pragma unroll
        for (int i = 1; i < 8; ++i) m = fmaxf(m, sh[i]);
        bc = m;
    }
    __syncthreads();
    mx = bc;
    float sum = 0.f;
#pragma unroll
    for (int it = 0; it < 8; ++it) {
        x[it] = expf(x[it] - mx);
        sum += x[it];
    }
    for (int o = 16; o; o >>= 1) sum += __shfl_xor_sync(0xffffffffu, sum, o);
    if ((tid & 31) == 0) sh[tid >> 5] = sum;
    __syncthreads();
    if (tid == 0) {
        float s2 = 0.f;
#pragma unroll
        for (int i = 0; i < 8; ++i) s2 += sh[i];
        bc = 1.f / s2;
    }
    __syncthreads();
    const float rinv = bc;
    const int tend = (s & ~127) + 128;     // 128-tile boundary zero-fill
#pragma unroll
    for (int it = 0; it < 8; ++it) {
        int t = tid + it * 256;
        if (t < n)            row[t] = x[it] * rinv;
        else if (t < tend)    row[t] = 0.f;
    }
}

// ---------------------------------------------------------------------------
// launch
// ---------------------------------------------------------------------------
extern "C" void kernel_launch(void* const* d_in, const int* in_sizes, int n_in,
                              void* d_out, int out_size)
{
    (void)in_sizes; (void)n_in; (void)out_size;
    const float* x        = (const float*)d_in[0];
    const int*   mask     = (const int*)  d_in[1];
    const float* wq_a_w   = (const float*)d_in[2];
    const float* wq_a_b   = (const float*)d_in[3];
    const float* q_norm_w = (const float*)d_in[4];
    const float* wq_b_w   = (const float*)d_in[5];
    const float* wq_b_b   = (const float*)d_in[6];
    const float* wkv_a_w  = (const float*)d_in[7];
    const float* wkv_a_b  = (const float*)d_in[8];
    const float* kv_norm_w= (const float*)d_in[9];
    const float* wkv_b_w  = (const float*)d_in[10];
    const float* wo_w     = (const float*)d_in[11];
    const float* wo_b     = (const float*)d_in[12];
    float* out = (float*)d_out;

    float *qa, *qn, *q, *kvf, *kc, *kvT, *wbt, *qc, *sc, *ol, *oh;
    cudaGetSymbolAddress((void**)&qa,  g_qa);
    cudaGetSymbolAddress((void**)&qn,  g_qn);
    cudaGetSymbolAddress((void**)&q,   g_q);
    cudaGetSymbolAddress((void**)&kvf, g_kvf);
    cudaGetSymbolAddress((void**)&kc,  g_kc);
    cudaGetSymbolAddress((void**)&kvT, g_kvT);
    cudaGetSymbolAddress((void**)&wbt, g_wbt);
    cudaGetSymbolAddress((void**)&qc,  g_qc);
    cudaGetSymbolAddress((void**)&sc,  g_sc);
    cudaGetSymbolAddress((void**)&ol,  g_ol);
    cudaGetSymbolAddress((void**)&oh,  g_oh);

    const dim3 blk(128);

    // q_a = x @ wq_a^T + b                         [4096,1536]
    gemm_tf32<<<dim3(12, 32, 1), blk>>>(x, 2048, 0, 0, wq_a_w, 2048, 0, 0,
                                        qa, 1536, 0, 0, 1536, 2048, wq_a_b, 1.f, 0);
    // rmsnorm
    rmsnorm_q_kernel<<<4096, 256>>>(q_norm_w);
    // q = qn @ wq_b^T + b                          [4096,3072]
    gemm_tf32<<<dim3(24, 32, 1), blk>>>(qn, 1536, 0, 0, wq_b_w, 1536, 0, 0,
                                        q, 3072, 0, 0, 3072, 1536, wq_b_b, 1.f, 0);
    // kv_full = x @ wkv_a^T + b                    [4096,576]  (ragged N)
    gemm_tf32<<<dim3(5, 32, 1), blk>>>(x, 2048, 0, 0, wkv_a_w, 2048, 0, 0,
                                       kvf, 576, 0, 0, 576, 2048, wkv_a_b, 1.f, 0);
    // kv rmsnorm + k_pe rope -> kc, kvT
    kv_prep_kernel<<<4096, 256>>>(kv_norm_w);
    // wkv_b nope-transpose
    wbt_kernel<<<4096, 256>>>(wkv_b_w);
    // q_pe rope + scale into qc[:,512:576]
    qpe_pack_kernel<<<8192, 256>>>();
    // q_lat = q_nope @ wkv_b[:, :128]^T  (scaled)  -> qc[:, :512]
    gemm_tf32<<<dim3(4, 16, 32), blk>>>(
        q, 3072, (long long)2048 * 3072, 192,
        wbt, 128, 0, (long long)512 * 128,
        qc, 576, (long long)16 * 2048 * 576, (long long)2048 * 576,
        512, 128, nullptr, SCALE_QK, 0);
    // scores = Qc @ Kc^T  (causal tile skip)
    gemm_tf32<<<dim3(16, 16, 32), blk>>>(
        qc, 576, (long long)16 * 2048 * 576, (long long)2048 * 576,
        kc, 576, (long long)2048 * 576, 0,
        sc, 2048, (long long)16 * 2048 * 2048, (long long)2048 * 2048,
        2048, 576, nullptr, 1.f, 1);
    // softmax (causal + mask)
    softmax_kernel<<<65536, 256>>>(mask);
    // out_lat = P @ V  (K clamped per 128-row query tile)
    gemm_tf32<<<dim3(4, 16, 32), blk>>>(
        sc, 2048, (long long)16 * 2048 * 2048, (long long)2048 * 2048,
        kvT, 2048, (long long)512 * 2048, 0,
        ol, 512, (long long)16 * 2048 * 512, (long long)2048 * 512,
        512, 2048, nullptr, 1.f, 2);
    // out_head[t, h*128+d] = out_lat @ wkv_b[:, 128:]^T
    gemm_tf32<<<dim3(1, 16, 32), blk>>>(
        ol, 512, (long long)16 * 2048 * 512, (long long)2048 * 512,
        wkv_b_w + 128 * 512, 512, 0, (long long)256 * 512,
        oh, 2048, (long long)2048 * 2048, 128,
        128, 512, nullptr, 1.f, 0);
    // out = out_head @ wo^T + b
    gemm_tf32<<<dim3(16, 32, 1), blk>>>(oh, 2048, 0, 0, wo_w, 2048, 0, 0,
                                        out, 2048, 0, 0, 2048, 2048, wo_b, 1.f, 0);
}

// round 12
// speedup vs baseline: 3.5516x; 1.0606x over previous
#include <cuda_runtime.h>
#include <cuda_bf16.h>
#include <math.h>

// ---------------------------------------------------------------------------
// Problem constants
//   B=2, S=2048, H=2048, NH=16, QL=1536, KVL=512, NOPE=128, ROPE=64, VD=128
//   QKH=192, scale = 1/sqrt(192)
// ---------------------------------------------------------------------------
#define SCALE_QK 0.07216878364870323f
#define ROPE_LF  0.28782313662425574f   /* ln(10000)/32 */

// ---------------------------------------------------------------------------
// Device scratch (static globals — no runtime allocation)
// ---------------------------------------------------------------------------
__device__ float g_qa [(size_t)4096 * 1536];          // x @ wq_a^T + b
__device__ float g_qn [(size_t)4096 * 1536];          // rmsnorm(qa), tf32
__device__ float g_q  [(size_t)4096 * 3072];          // qn @ wq_b^T + b, tf32
__device__ float g_kvf[(size_t)4096 * 576];           // x @ wkv_a^T + b
__device__ float g_kvp[(size_t)4 * 4096 * 576];       // split-K partials for kvf
__device__ float g_kc [(size_t)4096 * 576];           // [norm(kv) | rope(k_pe)], tf32
__device__ float g_kvT[(size_t)2 * 512 * 2048];       // per-batch V^T, tf32
__device__ float g_wbt[(size_t)16 * 512 * 128];       // wkv_b[:, :128] -> [h][c][d], tf32
__device__ float g_qc [(size_t)32 * 2048 * 576];      // scaled [q_lat | rope(q_pe)], tf32
__device__ float g_sc [(size_t)32 * 2048 * 2048];     // scores / probs (probs tf32)
__device__ float g_ol [(size_t)32 * 2048 * 512];      // attn @ V, tf32
__device__ float g_oh [(size_t)4096 * 2048];          // per-head out, tf32
// tf32-rounded copies of raw GEMM inputs
__device__ float g_xr  [(size_t)4096 * 2048];
__device__ float g_wqar[(size_t)1536 * 2048];
__device__ float g_wqbr[(size_t)3072 * 1536];
__device__ float g_wkvar[(size_t)576 * 2048];
__device__ float g_wor [(size_t)2048 * 2048];
__device__ float g_wbr [(size_t)4096 * 512];

// ---------------------------------------------------------------------------
// TF32 helpers
// ---------------------------------------------------------------------------
__device__ __forceinline__ unsigned f2tf32(float x) {
    unsigned r;
    asm("cvt.rna.tf32.f32 %0, %1;" : "=r"(r) : "f"(x));
    return r;
}
__device__ __forceinline__ float rtf(float x) { return __uint_as_float(f2tf32(x)); }
__device__ __forceinline__ float4 cvt4(float4 v) {
    v.x = rtf(v.x); v.y = rtf(v.y); v.z = rtf(v.z); v.w = rtf(v.w);
    return v;
}
// select component jj of a float4 (2 SELs)
__device__ __forceinline__ float pick4(float4 v, int jj) {
    float a = (jj & 1) ? v.y : v.x;
    float b = (jj & 1) ? v.w : v.z;
    return (jj & 2) ? b : a;
}
// Stage 4 values of one k-chunk into fragment-layout smem.
// Placement: dst[jj*4] = v[jj] (fixed); issue order rotated by `rot`
// per-thread so warp-wide STS spread across banks (2-way instead of 8-way).
__device__ __forceinline__ void stage4(float* dst, float4 v, int rot) {
#pragma unroll
    for (int t = 0; t < 4; ++t) {
        int jj = (t + rot) & 3;
        dst[jj * 4] = pick4(v, jj);
    }
}

// ---------------------------------------------------------------------------
// round a float4 array to tf32 (raw weight / activation pre-pass)
// ---------------------------------------------------------------------------
__global__ void round4_kernel(const float4* __restrict__ s, float4* __restrict__ d, int n4)
{
    int i = blockIdx.x * 256 + threadIdx.x;
    if (i < n4) d[i] = cvt4(s[i]);
}

// ---------------------------------------------------------------------------
// TF32 tensor-core NT GEMM:  C[m,n] = alpha * sum_k A[m,k]*B[n,k] (+ bias[n])
// All GEMM inputs are pre-rounded to tf32, so staging stores raw bits and the
// MMA's internal truncation is the identity (bit-identical to explicit cvt).
// CTA tile 128x128, BK=16, 128 threads (4 warps, 2x2 grid of 64x64 warp
// tiles), mma.m16n8k8.tf32, double-buffered, fragment-linear smem layout.
// flags bit0: causal tile skip (skip when bn0 >= bm0+128)
// flags bit1: K clamped to min(K, bm0+128)  (attn@V causal K clamp)
// flags bit2: round epilogue output to tf32 (output feeds another GEMM)
// ---------------------------------------------------------------------------
#define BM 128
#define BN 128
#define BK 16

__global__ void __launch_bounds__(128, 2)
gemm_tf32(const float* __restrict__ A, int lda, long long sAb, long long sAh,
          const float* __restrict__ B, int ldb, long long sBb, long long sBh,
          float* __restrict__ C, int ldc, long long sCb, long long sCh,
          int N, int K, const float* __restrict__ bias, float alpha, int flags)
{
    const long long zb = blockIdx.z >> 4;
    const long long zh = blockIdx.z & 15;
    const int bm0 = blockIdx.y * BM;
    const int bn0 = blockIdx.x * BN;
    if ((flags & 1) && bn0 >= bm0 + BM) return;
    const int Kl = (flags & 2) ? min(K, bm0 + BM) : K;

    A += zb * sAb + zh * sAh + (long long)bm0 * lda;
    B += zb * sBb + zh * sBh + (long long)bn0 * ldb;
    C += zb * sCb + zh * sCh;

    __shared__ float As[2 * 2048];
    __shared__ float Bs[2 * 2048];

    const int tid  = threadIdx.x;
    const int lane = tid & 31;
    const int warp = tid >> 5;         // 0..3
    const int wm   = warp >> 1;        // 0..1
    const int wn   = warp & 1;         // 0..1
    const int lq   = lane >> 2;        // 0..7
    const int lr   = lane & 3;         // 0..3

    // ---- staging-side indices ----
    const int lm   = tid >> 2;         // 0..31 : base tile row this thread loads
    const int lmo  = lm & 7;
    const int lk   = (tid & 3) * 4;    // 0,4,8,12
    const int kb_w = lk >> 3;          // k8-block
    const int kbit = (lk >> 2) & 1;    // reg bit from k
    const int rbit = (lm >> 3) & 1;    // same for lm+32*i
    const int rot  = lmo >> 1;

    const int baseA = (kb_w * 8 + (lm >> 4)) * 128 + lmo * 16 + rbit + 2 * kbit;
    const int baseB = (kb_w * 8 + (lm >> 4)) * 128 + lmo * 16 + 2 * rbit + kbit;

    // ---- consumer-side ----
    const int rd = lane * 4;

    const float* Ag = A + (long long)lm * lda + lk;
    const float* Bg = B + (long long)lm * ldb + lk;
    bool bv[4];
#pragma unroll
    for (int i = 0; i < 4; ++i) bv[i] = (bn0 + lm + 32 * i) < N;

    float acc[4][8][4];
#pragma unroll
    for (int i = 0; i < 4; ++i)
#pragma unroll
        for (int j = 0; j < 8; ++j)
#pragma unroll
            for (int r = 0; r < 4; ++r) acc[i][j][r] = 0.f;

    const int nK = Kl / BK;
    const float4 z4 = make_float4(0.f, 0.f, 0.f, 0.f);

    float4 ra[4], rb[4];
#pragma unroll
    for (int i = 0; i < 4; ++i) {
        ra[i] = *(const float4*)(Ag + (long long)(32 * i) * lda);
        rb[i] = bv[i] ? *(const float4*)(Bg + (long long)(32 * i) * ldb) : z4;
    }
#pragma unroll
    for (int i = 0; i < 4; ++i) {
        stage4(&As[baseA + i * 256], ra[i], rot);
        stage4(&Bs[baseB + i * 256], rb[i], rot);
    }
    __syncthreads();

    for (int kt = 0; kt < nK; ++kt) {
        const int sb = (kt & 1) * 2048;
        if (kt + 1 < nK) {
            const long long k0 = (kt + 1) * BK;
#pragma unroll
            for (int i = 0; i < 4; ++i) {
                ra[i] = *(const float4*)(Ag + (long long)(32 * i) * lda + k0);
                rb[i] = bv[i] ? *(const float4*)(Bg + (long long)(32 * i) * ldb + k0) : z4;
            }
        }
#pragma unroll
        for (int kb = 0; kb < 2; ++kb) {
            float4 a4[4], bp[4];
#pragma unroll
            for (int p = 0; p < 4; ++p)
                bp[p] = *(const float4*)&Bs[sb + (kb * 8 + wn * 4 + p) * 128 + rd];
#pragma unroll
            for (int mi = 0; mi < 4; ++mi)
                a4[mi] = *(const float4*)&As[sb + (kb * 8 + wm * 4 + mi) * 128 + rd];
#pragma unroll
            for (int mi = 0; mi < 4; ++mi)
#pragma unroll
                for (int p = 0; p < 4; ++p) {
                    asm volatile(
                        "mma.sync.aligned.m16n8k8.row.col.f32.tf32.tf32.f32 "
                        "{%0,%1,%2,%3}, {%4,%5,%6,%7}, {%8,%9}, {%0,%1,%2,%3};\n"
                        : "+f"(acc[mi][2 * p][0]), "+f"(acc[mi][2 * p][1]),
                          "+f"(acc[mi][2 * p][2]), "+f"(acc[mi][2 * p][3])
                        : "r"(__float_as_uint(a4[mi].x)), "r"(__float_as_uint(a4[mi].y)),
                          "r"(__float_as_uint(a4[mi].z)), "r"(__float_as_uint(a4[mi].w)),
                          "r"(__float_as_uint(bp[p].x)), "r"(__float_as_uint(bp[p].y)));
                    asm volatile(
                        "mma.sync.aligned.m16n8k8.row.col.f32.tf32.tf32.f32 "
                        "{%0,%1,%2,%3}, {%4,%5,%6,%7}, {%8,%9}, {%0,%1,%2,%3};\n"
                        : "+f"(acc[mi][2 * p + 1][0]), "+f"(acc[mi][2 * p + 1][1]),
                          "+f"(acc[mi][2 * p + 1][2]), "+f"(acc[mi][2 * p + 1][3])
                        : "r"(__float_as_uint(a4[mi].x)), "r"(__float_as_uint(a4[mi].y)),
                          "r"(__float_as_uint(a4[mi].z)), "r"(__float_as_uint(a4[mi].w)),
                          "r"(__float_as_uint(bp[p].z)), "r"(__float_as_uint(bp[p].w)));
                }
        }
        if (kt + 1 < nK) {
            const int nb = ((kt + 1) & 1) * 2048;
#pragma unroll
            for (int i = 0; i < 4; ++i) {
                stage4(&As[nb + baseA + i * 256], ra[i], rot);
                stage4(&Bs[nb + baseB + i * 256], rb[i], rot);
            }
        }
        __syncthreads();
    }

    // epilogue
    const bool rnd = (flags & 4) != 0;
#pragma unroll
    for (int mi = 0; mi < 4; ++mi) {
        const int r0 = bm0 + wm * 64 + mi * 16 + lq;
#pragma unroll
        for (int ni = 0; ni < 8; ++ni) {
            const int c0 = bn0 + wn * 64 + ni * 8 + 2 * lr;
            if (c0 < N) {
                float b0 = 0.f, b1 = 0.f;
                if (bias) { b0 = bias[c0]; b1 = bias[c0 + 1]; }
                float2 v;
                v.x = alpha * acc[mi][ni][0] + b0;
                v.y = alpha * acc[mi][ni][1] + b1;
                if (rnd) { v.x = rtf(v.x); v.y = rtf(v.y); }
                *(float2*)(C + (long long)r0 * ldc + c0) = v;
                v.x = alpha * acc[mi][ni][2] + b0;
                v.y = alpha * acc[mi][ni][3] + b1;
                if (rnd) { v.x = rtf(v.x); v.y = rtf(v.y); }
                *(float2*)(C + (long long)(r0 + 8) * ldc + c0) = v;
            }
        }
    }
}

// ---------------------------------------------------------------------------
// split-K reduce for kvf: sum 4 partials + bias
// ---------------------------------------------------------------------------
__global__ void kvf_reduce_kernel(const float* __restrict__ bias)
{
    const int i4 = blockIdx.x * 256 + threadIdx.x;     // 589824 float4 total
    const size_t stride4 = (size_t)4096 * 576 / 4;
    const float4* p = (const float4*)g_kvp;
    float4 a = p[i4];
    float4 b = p[i4 + stride4];
    float4 c = p[i4 + 2 * stride4];
    float4 d = p[i4 + 3 * stride4];
    float4 bv = *(const float4*)(bias + (i4 * 4) % 576);
    float4 o;
    o.x = a.x + b.x + c.x + d.x + bv.x;
    o.y = a.y + b.y + c.y + d.y + bv.y;
    o.z = a.z + b.z + c.z + d.z + bv.z;
    o.w = a.w + b.w + c.w + d.w + bv.w;
    ((float4*)g_kvf)[i4] = o;
}

// ---------------------------------------------------------------------------
// rmsnorm over QL=1536 (g_qa -> g_qn, tf32-rounded)
// ---------------------------------------------------------------------------
__global__ void rmsnorm_q_kernel(const float* __restrict__ w)
{
    const int t = blockIdx.x;
    const float* x = g_qa + (size_t)t * 1536;
    float* y = g_qn + (size_t)t * 1536;
    float v[6];
    float ss = 0.f;
#pragma unroll
    for (int i = 0; i < 6; ++i) {
        v[i] = x[threadIdx.x + i * 256];
        ss += v[i] * v[i];
    }
    __shared__ float sh[8];
    __shared__ float bc;
    for (int o = 16; o; o >>= 1) ss += __shfl_xor_sync(0xffffffffu, ss, o);
    if ((threadIdx.x & 31) == 0) sh[threadIdx.x >> 5] = ss;
    __syncthreads();
    if (threadIdx.x == 0) {
        float s2 = 0.f;
#pragma unroll
        for (int i = 0; i < 8; ++i) s2 += sh[i];
        bc = rsqrtf(s2 * (1.f / 1536.f) + 1e-6f);
    }
    __syncthreads();
    const float inv = bc;
#pragma unroll
    for (int i = 0; i < 6; ++i) {
        int j = threadIdx.x + i * 256;
        y[j] = rtf(w[j] * v[i] * inv);
    }
}

// ---------------------------------------------------------------------------
// kv prep: rmsnorm first 512 of g_kvf -> g_kc[:, :512] and g_kvT (transposed);
// rope last 64 -> g_kc[:, 512:576]. All outputs tf32-rounded.
// ---------------------------------------------------------------------------
__global__ void kv_prep_kernel(const float* __restrict__ w)
{
    const int t = blockIdx.x;
    const int b = t >> 11, s = t & 2047;
    const float* x = g_kvf + (size_t)t * 576;
    const int j0 = threadIdx.x, j1 = threadIdx.x + 256;
    float v0 = x[j0], v1 = x[j1];
    float ss = v0 * v0 + v1 * v1;
    __shared__ float sh[8];
    __shared__ float bc;
    for (int o = 16; o; o >>= 1) ss += __shfl_xor_sync(0xffffffffu, ss, o);
    if ((threadIdx.x & 31) == 0) sh[threadIdx.x >> 5] = ss;
    __syncthreads();
    if (threadIdx.x == 0) {
        float s2 = 0.f;
#pragma unroll
        for (int i = 0; i < 8; ++i) s2 += sh[i];
        bc = rsqrtf(s2 * (1.f / 512.f) + 1e-6f);
    }
    __syncthreads();
    const float inv = bc;
    float* kc = g_kc + (size_t)t * 576;
    float a0 = rtf(w[j0] * v0 * inv);
    float a1 = rtf(w[j1] * v1 * inv);
    kc[j0] = a0;
    kc[j1] = a1;
    g_kvT[((size_t)b * 512 + j0) * 2048 + s] = a0;
    g_kvT[((size_t)b * 512 + j1) * 2048 + s] = a1;
    if (threadIdx.x < 32) {
        int i = threadIdx.x;
        float p1 = x[512 + i], p2 = x[544 + i];
        float th = (float)s * expf(-(float)i * ROPE_LF);
        float sn, cs;
        sincosf(th, &sn, &cs);
        kc[512 + i] = rtf(p1 * cs - p2 * sn);
        kc[544 + i] = rtf(p2 * cs + p1 * sn);
    }
}

// ---------------------------------------------------------------------------
// rope q_pe + scale, packed into g_qc[:, 512:576] (tf32-rounded)
// ---------------------------------------------------------------------------
__global__ void qpe_pack_kernel()
{
    const int idx = blockIdx.x * 256 + threadIdx.x;
    const int i = idx & 31;
    const int h = (idx >> 5) & 15;
    const int t = idx >> 9;
    const int b = t >> 11, s = t & 2047;
    const float* qp = g_q + (size_t)t * 3072 + h * 192 + 128;
    float p1 = qp[i], p2 = qp[32 + i];
    float th = (float)s * expf(-(float)i * ROPE_LF);
    float sn, cs;
    sincosf(th, &sn, &cs);
    float* dst = g_qc + ((size_t)((b * 16 + h) * 2048 + s)) * 576 + 512;
    dst[i]      = rtf((p1 * cs - p2 * sn) * SCALE_QK);
    dst[32 + i] = rtf((p2 * cs + p1 * sn) * SCALE_QK);
}

// ---------------------------------------------------------------------------
// wkv_b[:, :128, :] -> g_wbt[h][c][d] (tf32-rounded)
// ---------------------------------------------------------------------------
__global__ void wbt_kernel(const float* __restrict__ w)
{
    const int idx = blockIdx.x * 256 + threadIdx.x;
    const int d = idx & 127;
    const int c = (idx >> 7) & 511;
    const int h = idx >> 16;
    g_wbt[idx] = rtf(w[((size_t)(h * 256 + d)) * 512 + c]);
}

// ---------------------------------------------------------------------------
// causal softmax over scores rows (in place). 65536 rows of length s+1.
// Probabilities tf32-rounded; zero-fills (s, next 128-boundary) so the
// K-clamped 128-tile attn@V GEMM reads valid zeros.
// ---------------------------------------------------------------------------
__global__ void softmax_kernel(const int* __restrict__ mask)
{
    const int rid = blockIdx.x;
    const int s = rid & 2047;
    const int b = rid >> 15;               // rid / (16*2048)
    float* row = g_sc + (size_t)rid * 2048;
    const int* mrow = mask + b * 2048;
    const int n = s + 1;
    const int tid = threadIdx.x;

    float x[8];
    float mx = -3.0e38f;
#pragma unroll
    for (int it = 0; it < 8; ++it) {
        int t = tid + it * 256;
        float v = -3.0e38f;
        if (t < n) v = row[t] + (mrow[t] == 0 ? -1e15f : 0.f);
        x[it] = v;
        mx = fmaxf(mx, v);
    }
    __shared__ float sh[8];
    __shared__ float bc;
    for (int o = 16; o; o >>= 1) mx = fmaxf(mx, __shfl_xor_sync(0xffffffffu, mx, o));
    if ((tid & 31) == 0) sh[tid >> 5] = mx;
    __syncthreads();
    if (tid == 0) {
        float m = sh[0];
#pragma unroll
        for (int i = 1; i < 8; ++i) m = fmaxf(m, sh[i]);
        bc = m;
    }
    __syncthreads();
    mx = bc;
    float sum = 0.f;
#pragma unroll
    for (int it = 0; it < 8; ++it) {
        x[it] = expf(x[it] - mx);
        sum += x[it];
    }
    for (int o = 16; o; o >>= 1) sum += __shfl_xor_sync(0xffffffffu, sum, o);
    if ((tid & 31) == 0) sh[tid >> 5] = sum;
    __syncthreads();
    if (tid == 0) {
        float s2 = 0.f;
#pragma unroll
        for (int i = 0; i < 8; ++i) s2 += sh[i];
        bc = 1.f / s2;
    }
    __syncthreads();
    const float rinv = bc;
    const int tend = (s & ~127) + 128;     // 128-tile boundary zero-fill
#pragma unroll
    for (int it = 0; it < 8; ++it) {
        int t = tid + it * 256;
        if (t < n)            row[t] = rtf(x[it] * rinv);
        else if (t < tend)    row[t] = 0.f;
    }
}

// ---------------------------------------------------------------------------
// launch
// ---------------------------------------------------------------------------
extern "C" void kernel_launch(void* const* d_in, const int* in_sizes, int n_in,
                              void* d_out, int out_size)
{
    (void)in_sizes; (void)n_in; (void)out_size;
    const float* x        = (const float*)d_in[0];
    const int*   mask     = (const int*)  d_in[1];
    const float* wq_a_w   = (const float*)d_in[2];
    const float* wq_a_b   = (const float*)d_in[3];
    const float* q_norm_w = (const float*)d_in[4];
    const float* wq_b_w   = (const float*)d_in[5];
    const float* wq_b_b   = (const float*)d_in[6];
    const float* wkv_a_w  = (const float*)d_in[7];
    const float* wkv_a_b  = (const float*)d_in[8];
    const float* kv_norm_w= (const float*)d_in[9];
    const float* wkv_b_w  = (const float*)d_in[10];
    const float* wo_w     = (const float*)d_in[11];
    const float* wo_b     = (const float*)d_in[12];
    float* out = (float*)d_out;

    float *qa, *qn, *q, *kvf, *kvp, *kc, *kvT, *wbt, *qc, *sc, *ol, *oh;
    float *xr, *wqar, *wqbr, *wkvar, *wor, *wbr;
    cudaGetSymbolAddress((void**)&qa,  g_qa);
    cudaGetSymbolAddress((void**)&qn,  g_qn);
    cudaGetSymbolAddress((void**)&q,   g_q);
    cudaGetSymbolAddress((void**)&kvf, g_kvf);
    cudaGetSymbolAddress((void**)&kvp, g_kvp);
    cudaGetSymbolAddress((void**)&kc,  g_kc);
    cudaGetSymbolAddress((void**)&kvT, g_kvT);
    cudaGetSymbolAddress((void**)&wbt, g_wbt);
    cudaGetSymbolAddress((void**)&qc,  g_qc);
    cudaGetSymbolAddress((void**)&sc,  g_sc);
    cudaGetSymbolAddress((void**)&ol,  g_ol);
    cudaGetSymbolAddress((void**)&oh,  g_oh);
    cudaGetSymbolAddress((void**)&xr,   g_xr);
    cudaGetSymbolAddress((void**)&wqar, g_wqar);
    cudaGetSymbolAddress((void**)&wqbr, g_wqbr);
    cudaGetSymbolAddress((void**)&wkvar,g_wkvar);
    cudaGetSymbolAddress((void**)&wor,  g_wor);
    cudaGetSymbolAddress((void**)&wbr,  g_wbr);

    const dim3 blk(128);

    // ---- pre-round raw GEMM inputs to tf32 ----
    round4_kernel<<<8192, 256>>>((const float4*)x,      (float4*)xr,    2097152);
    round4_kernel<<<3072, 256>>>((const float4*)wq_a_w, (float4*)wqar,   786432);
    round4_kernel<<<4608, 256>>>((const float4*)wq_b_w, (float4*)wqbr,  1179648);
    round4_kernel<<<1152, 256>>>((const float4*)wkv_a_w,(float4*)wkvar,  294912);
    round4_kernel<<<4096, 256>>>((const float4*)wo_w,   (float4*)wor,   1048576);
    round4_kernel<<<2048, 256>>>((const float4*)wkv_b_w,(float4*)wbr,    524288);

    // q_a = x @ wq_a^T + b                         [4096,1536]
    gemm_tf32<<<dim3(12, 32, 1), blk>>>(xr, 2048, 0, 0, wqar, 2048, 0, 0,
                                        qa, 1536, 0, 0, 1536, 2048, wq_a_b, 1.f, 0);
    // rmsnorm (tf32 out)
    rmsnorm_q_kernel<<<4096, 256>>>(q_norm_w);
    // q = qn @ wq_b^T + b                          [4096,3072] (tf32 out)
    gemm_tf32<<<dim3(24, 32, 1), blk>>>(qn, 1536, 0, 0, wqbr, 1536, 0, 0,
                                        q, 3072, 0, 0, 3072, 1536, wq_b_b, 1.f, 4);
    // kv_full = x @ wkv_a^T  split-K x4 -> partials (z = k-slice)
    gemm_tf32<<<dim3(5, 32, 4), blk>>>(xr, 2048, 0, 512, wkvar, 2048, 0, 512,
                                       kvp, 576, 0, (long long)4096 * 576,
                                       576, 512, nullptr, 1.f, 0);
    kvf_reduce_kernel<<<2304, 256>>>(wkv_a_b);
    // kv rmsnorm + k_pe rope -> kc, kvT (tf32 out)
    kv_prep_kernel<<<4096, 256>>>(kv_norm_w);
    // wkv_b nope-transpose (tf32 out)
    wbt_kernel<<<4096, 256>>>(wkv_b_w);
    // q_pe rope + scale into qc[:,512:576] (tf32 out)
    qpe_pack_kernel<<<8192, 256>>>();
    // q_lat = q_nope @ wkv_b[:, :128]^T  (scaled)  -> qc[:, :512] (tf32 out)
    gemm_tf32<<<dim3(4, 16, 32), blk>>>(
        q, 3072, (long long)2048 * 3072, 192,
        wbt, 128, 0, (long long)512 * 128,
        qc, 576, (long long)16 * 2048 * 576, (long long)2048 * 576,
        512, 128, nullptr, SCALE_QK, 4);
    // scores = Qc @ Kc^T  (causal tile skip)
    gemm_tf32<<<dim3(16, 16, 32), blk>>>(
        qc, 576, (long long)16 * 2048 * 576, (long long)2048 * 576,
        kc, 576, (long long)2048 * 576, 0,
        sc, 2048, (long long)16 * 2048 * 2048, (long long)2048 * 2048,
        2048, 576, nullptr, 1.f, 1);
    // softmax (causal + mask, tf32 probs)
    softmax_kernel<<<65536, 256>>>(mask);
    // out_lat = P @ V  (K clamped per 128-row query tile, tf32 out)
    gemm_tf32<<<dim3(4, 16, 32), blk>>>(
        sc, 2048, (long long)16 * 2048 * 2048, (long long)2048 * 2048,
        kvT, 2048, (long long)512 * 2048, 0,
        ol, 512, (long long)16 * 2048 * 512, (long long)2048 * 512,
        512, 2048, nullptr, 1.f, 2 | 4);
    // out_head[t, h*128+d] = out_lat @ wkv_b[:, 128:]^T (tf32 out)
    gemm_tf32<<<dim3(1, 16, 32), blk>>>(
        ol, 512, (long long)16 * 2048 * 512, (long long)2048 * 512,
        wbr + 128 * 512, 512, 0, (long long)256 * 512,
        oh, 2048, (long long)2048 * 2048, 128,
        128, 512, nullptr, 1.f, 4);
    // out = out_head @ wo^T + b (full fp32 out)
    gemm_tf32<<<dim3(16, 32, 1), blk>>>(oh, 2048, 0, 0, wor, 2048, 0, 0,
                                        out, 2048, 0, 0, 2048, 2048, wo_b, 1.f, 0);
}

// round 16
// speedup vs baseline: 3.6290x; 1.0218x over previous
#include <cuda_runtime.h>
#include <cuda_bf16.h>
#include <math.h>

// ---------------------------------------------------------------------------
// Problem constants
//   B=2, S=2048, H=2048, NH=16, QL=1536, KVL=512, NOPE=128, ROPE=64, VD=128
//   QKH=192, scale = 1/sqrt(192)
// ---------------------------------------------------------------------------
#define SCALE_QK 0.07216878364870323f
#define ROPE_LF  0.28782313662425574f   /* ln(10000)/32 */

// ---------------------------------------------------------------------------
// Device scratch (static globals — no runtime allocation)
// ---------------------------------------------------------------------------
__device__ float g_qa [(size_t)4096 * 1536];          // x @ wq_a^T + b
__device__ float g_qn [(size_t)4096 * 1536];          // rmsnorm(qa), tf32
__device__ float g_q  [(size_t)4096 * 3072];          // qn @ wq_b^T + b, tf32
__device__ float g_kvf[(size_t)4096 * 576];           // x @ wkv_a^T + b
__device__ float g_kvp[(size_t)4 * 4096 * 576];       // split-K partials for kvf
__device__ float g_kc [(size_t)4096 * 576];           // [norm(kv) | rope(k_pe)], tf32
__device__ float g_kvT[(size_t)2 * 512 * 2048];       // per-batch V^T, tf32
__device__ float g_wbt[(size_t)16 * 512 * 128];       // wkv_b[:, :128] -> [h][c][d], tf32
__device__ float g_qc [(size_t)32 * 2048 * 576];      // scaled [q_lat | rope(q_pe)], tf32
__device__ float g_sc [(size_t)32 * 2048 * 2048];     // scores / probs (probs tf32)
__device__ float g_ol [(size_t)32 * 2048 * 512];      // attn @ V, tf32
__device__ float g_oh [(size_t)4096 * 2048];          // per-head out, tf32
// tf32-rounded copies of raw GEMM inputs
__device__ float g_xr  [(size_t)4096 * 2048];
__device__ float g_wqar[(size_t)1536 * 2048];
__device__ float g_wqbr[(size_t)3072 * 1536];
__device__ float g_wkvar[(size_t)576 * 2048];
__device__ float g_wor [(size_t)2048 * 2048];
__device__ float g_wbr [(size_t)4096 * 512];

// ---------------------------------------------------------------------------
// TF32 helpers
// ---------------------------------------------------------------------------
__device__ __forceinline__ unsigned f2tf32(float x) {
    unsigned r;
    asm("cvt.rna.tf32.f32 %0, %1;" : "=r"(r) : "f"(x));
    return r;
}
__device__ __forceinline__ float rtf(float x) { return __uint_as_float(f2tf32(x)); }
__device__ __forceinline__ float4 cvt4(float4 v) {
    v.x = rtf(v.x); v.y = rtf(v.y); v.z = rtf(v.z); v.w = rtf(v.w);
    return v;
}
// Store one k-chunk (4 scalars) at 4 precomputed permuted offsets — no SELs.
__device__ __forceinline__ void stage4p(float* s, const int* off, float4 v) {
    s[off[0]] = v.x;
    s[off[1]] = v.y;
    s[off[2]] = v.z;
    s[off[3]] = v.w;
}

// ---------------------------------------------------------------------------
// single fused tf32 pre-round pass over all raw GEMM inputs
// ---------------------------------------------------------------------------
__global__ void round_all_kernel(const float4* __restrict__ x,
                                 const float4* __restrict__ wqa,
                                 const float4* __restrict__ wqb,
                                 const float4* __restrict__ wkva,
                                 const float4* __restrict__ wo,
                                 const float4* __restrict__ wb)
{
    long long i = (long long)blockIdx.x * 256 + threadIdx.x;
    if (i < 2097152) { ((float4*)g_xr)[i] = cvt4(x[i]); return; }
    i -= 2097152;
    if (i < 786432)  { ((float4*)g_wqar)[i] = cvt4(wqa[i]); return; }
    i -= 786432;
    if (i < 1179648) { ((float4*)g_wqbr)[i] = cvt4(wqb[i]); return; }
    i -= 1179648;
    if (i < 294912)  { ((float4*)g_wkvar)[i] = cvt4(wkva[i]); return; }
    i -= 294912;
    if (i < 1048576) { ((float4*)g_wor)[i] = cvt4(wo[i]); return; }
    i -= 1048576;
    if (i < 524288)  { ((float4*)g_wbr)[i] = cvt4(wb[i]); }
}

// ---------------------------------------------------------------------------
// TF32 tensor-core NT GEMM:  C[m,n] = alpha * sum_k A[m,k]*B[n,k] (+ bias[n])
// All GEMM inputs are pre-rounded to tf32 (MMA truncation = identity).
// CTA tile 128x128, BK=16, 128 threads (4 warps, 2x2 grid of 64x64 warp
// tiles), mma.m16n8k8.tf32, double-buffered, fragment-linear smem layout
// with an address-space lane permutation: within each 4-lane group, lane L's
// fragment float4 lives at slot (L + rot)&3 where rot = L>>3. Staging threads
// store their 4 k-values at 4 precomputed offsets (zero SEL overhead);
// consumers read at perm(lane). Bank behavior identical to the old rotation.
// flags bit0: causal tile skip (skip when bn0 >= bm0+128)
// flags bit1: K clamped to min(K, bm0+128)  (attn@V causal K clamp)
// flags bit2: round epilogue output to tf32 (output feeds another GEMM)
// ---------------------------------------------------------------------------
#define BM 128
#define BN 128
#define BK 16

__global__ void __launch_bounds__(128, 2)
gemm_tf32(const float* __restrict__ A, int lda, long long sAb, long long sAh,
          const float* __restrict__ B, int ldb, long long sBb, long long sBh,
          float* __restrict__ C, int ldc, long long sCb, long long sCh,
          int N, int K, const float* __restrict__ bias, float alpha, int flags)
{
    const long long zb = blockIdx.z >> 4;
    const long long zh = blockIdx.z & 15;
    const int bm0 = blockIdx.y * BM;
    const int bn0 = blockIdx.x * BN;
    if ((flags & 1) && bn0 >= bm0 + BM) return;
    const int Kl = (flags & 2) ? min(K, bm0 + BM) : K;

    A += zb * sAb + zh * sAh + (long long)bm0 * lda;
    B += zb * sBb + zh * sBh + (long long)bn0 * ldb;
    C += zb * sCb + zh * sCh;

    __shared__ float As[2 * 2048];
    __shared__ float Bs[2 * 2048];

    const int tid  = threadIdx.x;
    const int lane = tid & 31;
    const int warp = tid >> 5;         // 0..3
    const int wm   = warp >> 1;        // 0..1
    const int wn   = warp & 1;         // 0..1
    const int lq   = lane >> 2;        // 0..7
    const int lr   = lane & 3;         // 0..3

    // ---- staging-side indices ----
    const int lm   = tid >> 2;         // 0..31 : base tile row this thread loads
    const int lmo  = lm & 7;
    const int lk   = (tid & 3) * 4;    // 0,4,8,12
    const int kb_w = lk >> 3;          // k8-block
    const int kbit = (lk >> 2) & 1;    // reg bit from k
    const int rbit = (lm >> 3) & 1;    // same for lm+32*i
    const int rot  = lmo >> 1;

    // precomputed permuted store offsets: value jj -> slot (jj+rot)&3
    const int fragb = (kb_w * 8 + (lm >> 4)) * 128 + lmo * 16;
    int offA[4], offB[4];
#pragma unroll
    for (int jj = 0; jj < 4; ++jj) {
        const int slot = ((jj + rot) & 3) * 4;
        offA[jj] = fragb + slot + rbit + 2 * kbit;
        offB[jj] = fragb + slot + 2 * rbit + kbit;
    }

    // ---- consumer-side: permuted lane read address ----
    const int rd = (((lane & ~3) | ((lane + (lane >> 3)) & 3))) * 4;

    const float* Ag = A + (long long)lm * lda + lk;
    const float* Bg = B + (long long)lm * ldb + lk;
    bool bv[4];
#pragma unroll
    for (int i = 0; i < 4; ++i) bv[i] = (bn0 + lm + 32 * i) < N;

    float acc[4][8][4];
#pragma unroll
    for (int i = 0; i < 4; ++i)
#pragma unroll
        for (int j = 0; j < 8; ++j)
#pragma unroll
            for (int r = 0; r < 4; ++r) acc[i][j][r] = 0.f;

    const int nK = Kl / BK;
    const float4 z4 = make_float4(0.f, 0.f, 0.f, 0.f);

    float4 ra[4], rb[4];
#pragma unroll
    for (int i = 0; i < 4; ++i) {
        ra[i] = *(const float4*)(Ag + (long long)(32 * i) * lda);
        rb[i] = bv[i] ? *(const float4*)(Bg + (long long)(32 * i) * ldb) : z4;
    }
#pragma unroll
    for (int i = 0; i < 4; ++i) {
        stage4p(As + i * 256, offA, ra[i]);
        stage4p(Bs + i * 256, offB, rb[i]);
    }
    __syncthreads();

    for (int kt = 0; kt < nK; ++kt) {
        const int sb = (kt & 1) * 2048;
        if (kt + 1 < nK) {
            const long long k0 = (kt + 1) * BK;
#pragma unroll
            for (int i = 0; i < 4; ++i) {
                ra[i] = *(const float4*)(Ag + (long long)(32 * i) * lda + k0);
                rb[i] = bv[i] ? *(const float4*)(Bg + (long long)(32 * i) * ldb + k0) : z4;
            }
        }
#pragma unroll
        for (int kb = 0; kb < 2; ++kb) {
            float4 a4[4], bp[4];
#pragma unroll
            for (int p = 0; p < 4; ++p)
                bp[p] = *(const float4*)&Bs[sb + (kb * 8 + wn * 4 + p) * 128 + rd];
#pragma unroll
            for (int mi = 0; mi < 4; ++mi)
                a4[mi] = *(const float4*)&As[sb + (kb * 8 + wm * 4 + mi) * 128 + rd];
#pragma unroll
            for (int mi = 0; mi < 4; ++mi)
#pragma unroll
                for (int p = 0; p < 4; ++p) {
                    asm volatile(
                        "mma.sync.aligned.m16n8k8.row.col.f32.tf32.tf32.f32 "
                        "{%0,%1,%2,%3}, {%4,%5,%6,%7}, {%8,%9}, {%0,%1,%2,%3};\n"
                        : "+f"(acc[mi][2 * p][0]), "+f"(acc[mi][2 * p][1]),
                          "+f"(acc[mi][2 * p][2]), "+f"(acc[mi][2 * p][3])
                        : "r"(__float_as_uint(a4[mi].x)), "r"(__float_as_uint(a4[mi].y)),
                          "r"(__float_as_uint(a4[mi].z)), "r"(__float_as_uint(a4[mi].w)),
                          "r"(__float_as_uint(bp[p].x)), "r"(__float_as_uint(bp[p].y)));
                    asm volatile(
                        "mma.sync.aligned.m16n8k8.row.col.f32.tf32.tf32.f32 "
                        "{%0,%1,%2,%3}, {%4,%5,%6,%7}, {%8,%9}, {%0,%1,%2,%3};\n"
                        : "+f"(acc[mi][2 * p + 1][0]), "+f"(acc[mi][2 * p + 1][1]),
                          "+f"(acc[mi][2 * p + 1][2]), "+f"(acc[mi][2 * p + 1][3])
                        : "r"(__float_as_uint(a4[mi].x)), "r"(__float_as_uint(a4[mi].y)),
                          "r"(__float_as_uint(a4[mi].z)), "r"(__float_as_uint(a4[mi].w)),
                          "r"(__float_as_uint(bp[p].z)), "r"(__float_as_uint(bp[p].w)));
                }
        }
        if (kt + 1 < nK) {
            const int nb = ((kt + 1) & 1) * 2048;
#pragma unroll
            for (int i = 0; i < 4; ++i) {
                stage4p(As + nb + i * 256, offA, ra[i]);
                stage4p(Bs + nb + i * 256, offB, rb[i]);
            }
        }
        __syncthreads();
    }

    // epilogue
    const bool rnd = (flags & 4) != 0;
#pragma unroll
    for (int mi = 0; mi < 4; ++mi) {
        const int r0 = bm0 + wm * 64 + mi * 16 + lq;
#pragma unroll
        for (int ni = 0; ni < 8; ++ni) {
            const int c0 = bn0 + wn * 64 + ni * 8 + 2 * lr;
            if (c0 < N) {
                float b0 = 0.f, b1 = 0.f;
                if (bias) { b0 = bias[c0]; b1 = bias[c0 + 1]; }
                float2 v;
                v.x = alpha * acc[mi][ni][0] + b0;
                v.y = alpha * acc[mi][ni][1] + b1;
                if (rnd) { v.x = rtf(v.x); v.y = rtf(v.y); }
                *(float2*)(C + (long long)r0 * ldc + c0) = v;
                v.x = alpha * acc[mi][ni][2] + b0;
                v.y = alpha * acc[mi][ni][3] + b1;
                if (rnd) { v.x = rtf(v.x); v.y = rtf(v.y); }
                *(float2*)(C + (long long)(r0 + 8) * ldc + c0) = v;
            }
        }
    }
}

// ---------------------------------------------------------------------------
// split-K reduce for kvf: sum 4 partials + bias
// ---------------------------------------------------------------------------
__global__ void kvf_reduce_kernel(const float* __restrict__ bias)
{
    const int i4 = blockIdx.x * 256 + threadIdx.x;     // 589824 float4 total
    const size_t stride4 = (size_t)4096 * 576 / 4;
    const float4* p = (const float4*)g_kvp;
    float4 a = p[i4];
    float4 b = p[i4 + stride4];
    float4 c = p[i4 + 2 * stride4];
    float4 d = p[i4 + 3 * stride4];
    float4 bv = *(const float4*)(bias + (i4 * 4) % 576);
    float4 o;
    o.x = a.x + b.x + c.x + d.x + bv.x;
    o.y = a.y + b.y + c.y + d.y + bv.y;
    o.z = a.z + b.z + c.z + d.z + bv.z;
    o.w = a.w + b.w + c.w + d.w + bv.w;
    ((float4*)g_kvf)[i4] = o;
}

// ---------------------------------------------------------------------------
// rmsnorm over QL=1536 (g_qa -> g_qn, tf32-rounded)
// ---------------------------------------------------------------------------
__global__ void rmsnorm_q_kernel(const float* __restrict__ w)
{
    const int t = blockIdx.x;
    const float* x = g_qa + (size_t)t * 1536;
    float* y = g_qn + (size_t)t * 1536;
    float v[6];
    float ss = 0.f;
#pragma unroll
    for (int i = 0; i < 6; ++i) {
        v[i] = x[threadIdx.x + i * 256];
        ss += v[i] * v[i];
    }
    __shared__ float sh[8];
    __shared__ float bc;
    for (int o = 16; o; o >>= 1) ss += __shfl_xor_sync(0xffffffffu, ss, o);
    if ((threadIdx.x & 31) == 0) sh[threadIdx.x >> 5] = ss;
    __syncthreads();
    if (threadIdx.x == 0) {
        float s2 = 0.f;
#pragma unroll
        for (int i = 0; i < 8; ++i) s2 += sh[i];
        bc = rsqrtf(s2 * (1.f / 1536.f) + 1e-6f);
    }
    __syncthreads();
    const float inv = bc;
#pragma unroll
    for (int i = 0; i < 6; ++i) {
        int j = threadIdx.x + i * 256;
        y[j] = rtf(w[j] * v[i] * inv);
    }
}

// ---------------------------------------------------------------------------
// kv prep: rmsnorm first 512 of g_kvf -> g_kc[:, :512] and g_kvT (transposed);
// rope last 64 -> g_kc[:, 512:576]. All outputs tf32-rounded.
// ---------------------------------------------------------------------------
__global__ void kv_prep_kernel(const float* __restrict__ w)
{
    const int t = blockIdx.x;
    const int b = t >> 11, s = t & 2047;
    const float* x = g_kvf + (size_t)t * 576;
    const int j0 = threadIdx.x, j1 = threadIdx.x + 256;
    float v0 = x[j0], v1 = x[j1];
    float ss = v0 * v0 + v1 * v1;
    __shared__ float sh[8];
    __shared__ float bc;
    for (int o = 16; o; o >>= 1) ss += __shfl_xor_sync(0xffffffffu, ss, o);
    if ((threadIdx.x & 31) == 0) sh[threadIdx.x >> 5] = ss;
    __syncthreads();
    if (threadIdx.x == 0) {
        float s2 = 0.f;
#pragma unroll
        for (int i = 0; i < 8; ++i) s2 += sh[i];
        bc = rsqrtf(s2 * (1.f / 512.f) + 1e-6f);
    }
    __syncthreads();
    const float inv = bc;
    float* kc = g_kc + (size_t)t * 576;
    float a0 = rtf(w[j0] * v0 * inv);
    float a1 = rtf(w[j1] * v1 * inv);
    kc[j0] = a0;
    kc[j1] = a1;
    g_kvT[((size_t)b * 512 + j0) * 2048 + s] = a0;
    g_kvT[((size_t)b * 512 + j1) * 2048 + s] = a1;
    if (threadIdx.x < 32) {
        int i = threadIdx.x;
        float p1 = x[512 + i], p2 = x[544 + i];
        float th = (float)s * expf(-(float)i * ROPE_LF);
        float sn, cs;
        sincosf(th, &sn, &cs);
        kc[512 + i] = rtf(p1 * cs - p2 * sn);
        kc[544 + i] = rtf(p2 * cs + p1 * sn);
    }
}

// ---------------------------------------------------------------------------
// rope q_pe + scale, packed into g_qc[:, 512:576] (tf32-rounded)
// ---------------------------------------------------------------------------
__global__ void qpe_pack_kernel()
{
    const int idx = blockIdx.x * 256 + threadIdx.x;
    const int i = idx & 31;
    const int h = (idx >> 5) & 15;
    const int t = idx >> 9;
    const int b = t >> 11, s = t & 2047;
    const float* qp = g_q + (size_t)t * 3072 + h * 192 + 128;
    float p1 = qp[i], p2 = qp[32 + i];
    float th = (float)s * expf(-(float)i * ROPE_LF);
    float sn, cs;
    sincosf(th, &sn, &cs);
    float* dst = g_qc + ((size_t)((b * 16 + h) * 2048 + s)) * 576 + 512;
    dst[i]      = rtf((p1 * cs - p2 * sn) * SCALE_QK);
    dst[32 + i] = rtf((p2 * cs + p1 * sn) * SCALE_QK);
}

// ---------------------------------------------------------------------------
// wkv_b[:, :128, :] -> g_wbt[h][c][d] (tf32-rounded)
// ---------------------------------------------------------------------------
__global__ void wbt_kernel(const float* __restrict__ w)
{
    const int idx = blockIdx.x * 256 + threadIdx.x;
    const int d = idx & 127;
    const int c = (idx >> 7) & 511;
    const int h = idx >> 16;
    g_wbt[idx] = rtf(w[((size_t)(h * 256 + d)) * 512 + c]);
}

// ---------------------------------------------------------------------------
// causal softmax over scores rows (in place). 65536 rows of length s+1.
// Probabilities tf32-rounded; zero-fills (s, next 128-boundary) so the
// K-clamped 128-tile attn@V GEMM reads valid zeros.
// ---------------------------------------------------------------------------
__global__ void softmax_kernel(const int* __restrict__ mask)
{
    const int rid = blockIdx.x;
    const int s = rid & 2047;
    const int b = rid >> 15;               // rid / (16*2048)
    float* row = g_sc + (size_t)rid * 2048;
    const int* mrow = mask + b * 2048;
    const int n = s + 1;
    const int tid = threadIdx.x;

    float x[8];
    float mx = -3.0e38f;
#pragma unroll
    for (int it = 0; it < 8; ++it) {
        int t = tid + it * 256;
        float v = -3.0e38f;
        if (t < n) v = row[t] + (mrow[t] == 0 ? -1e15f : 0.f);
        x[it] = v;
        mx = fmaxf(mx, v);
    }
    __shared__ float sh[8];
    __shared__ float bc;
    for (int o = 16; o; o >>= 1) mx = fmaxf(mx, __shfl_xor_sync(0xffffffffu, mx, o));
    if ((tid & 31) == 0) sh[tid >> 5] = mx;
    __syncthreads();
    if (tid == 0) {
        float m = sh[0];
#pragma unroll
        for (int i = 1; i < 8; ++i) m = fmaxf(m, sh[i]);
        bc = m;
    }
    __syncthreads();
    mx = bc;
    float sum = 0.f;
#pragma unroll
    for (int it = 0; it < 8; ++it) {
        x[it] = expf(x[it] - mx);
        sum += x[it];
    }
    for (int o = 16; o; o >>= 1) sum += __shfl_xor_sync(0xffffffffu, sum, o);
    if ((tid & 31) == 0) sh[tid >> 5] = sum;
    __syncthreads();
    if (tid == 0) {
        float s2 = 0.f;
#pragma unroll
        for (int i = 0; i < 8; ++i) s2 += sh[i];
        bc = 1.f / s2;
    }
    __syncthreads();
    const float rinv = bc;
    const int tend = (s & ~127) + 128;     // 128-tile boundary zero-fill
#pragma unroll
    for (int it = 0; it < 8; ++it) {
        int t = tid + it * 256;
        if (t < n)            row[t] = rtf(x[it] * rinv);
        else if (t < tend)    row[t] = 0.f;
    }
}

// ---------------------------------------------------------------------------
// launch
// ---------------------------------------------------------------------------
extern "C" void kernel_launch(void* const* d_in, const int* in_sizes, int n_in,
                              void* d_out, int out_size)
{
    (void)in_sizes; (void)n_in; (void)out_size;
    const float* x        = (const float*)d_in[0];
    const int*   mask     = (const int*)  d_in[1];
    const float* wq_a_w   = (const float*)d_in[2];
    const float* wq_a_b   = (const float*)d_in[3];
    const float* q_norm_w = (const float*)d_in[4];
    const float* wq_b_w   = (const float*)d_in[5];
    const float* wq_b_b   = (const float*)d_in[6];
    const float* wkv_a_w  = (const float*)d_in[7];
    const float* wkv_a_b  = (const float*)d_in[8];
    const float* kv_norm_w= (const float*)d_in[9];
    const float* wkv_b_w  = (const float*)d_in[10];
    const float* wo_w     = (const float*)d_in[11];
    const float* wo_b     = (const float*)d_in[12];
    float* out = (float*)d_out;

    float *qa, *qn, *q, *kvf, *kvp, *kc, *kvT, *wbt, *qc, *sc, *ol, *oh;
    float *xr, *wqar, *wqbr, *wkvar, *wor, *wbr;
    cudaGetSymbolAddress((void**)&qa,  g_qa);
    cudaGetSymbolAddress((void**)&qn,  g_qn);
    cudaGetSymbolAddress((void**)&q,   g_q);
    cudaGetSymbolAddress((void**)&kvf, g_kvf);
    cudaGetSymbolAddress((void**)&kvp, g_kvp);
    cudaGetSymbolAddress((void**)&kc,  g_kc);
    cudaGetSymbolAddress((void**)&kvT, g_kvT);
    cudaGetSymbolAddress((void**)&wbt, g_wbt);
    cudaGetSymbolAddress((void**)&qc,  g_qc);
    cudaGetSymbolAddress((void**)&sc,  g_sc);
    cudaGetSymbolAddress((void**)&ol,  g_ol);
    cudaGetSymbolAddress((void**)&oh,  g_oh);
    cudaGetSymbolAddress((void**)&xr,   g_xr);
    cudaGetSymbolAddress((void**)&wqar, g_wqar);
    cudaGetSymbolAddress((void**)&wqbr, g_wqbr);
    cudaGetSymbolAddress((void**)&wkvar,g_wkvar);
    cudaGetSymbolAddress((void**)&wor,  g_wor);
    cudaGetSymbolAddress((void**)&wbr,  g_wbr);

    const dim3 blk(128);

    // ---- fused tf32 pre-round of all raw GEMM inputs (5,931,008 float4) ----
    round_all_kernel<<<23168, 256>>>((const float4*)x, (const float4*)wq_a_w,
                                     (const float4*)wq_b_w, (const float4*)wkv_a_w,
                                     (const float4*)wo_w, (const float4*)wkv_b_w);

    // q_a = x @ wq_a^T + b                         [4096,1536]
    gemm_tf32<<<dim3(12, 32, 1), blk>>>(xr, 2048, 0, 0, wqar, 2048, 0, 0,
                                        qa, 1536, 0, 0, 1536, 2048, wq_a_b, 1.f, 0);
    // rmsnorm (tf32 out)
    rmsnorm_q_kernel<<<4096, 256>>>(q_norm_w);
    // q = qn @ wq_b^T + b                          [4096,3072] (tf32 out)
    gemm_tf32<<<dim3(24, 32, 1), blk>>>(qn, 1536, 0, 0, wqbr, 1536, 0, 0,
                                        q, 3072, 0, 0, 3072, 1536, wq_b_b, 1.f, 4);
    // kv_full = x @ wkv_a^T  split-K x4 -> partials (z = k-slice)
    gemm_tf32<<<dim3(5, 32, 4), blk>>>(xr, 2048, 0, 512, wkvar, 2048, 0, 512,
                                       kvp, 576, 0, (long long)4096 * 576,
                                       576, 512, nullptr, 1.f, 0);
    kvf_reduce_kernel<<<2304, 256>>>(wkv_a_b);
    // kv rmsnorm + k_pe rope -> kc, kvT (tf32 out)
    kv_prep_kernel<<<4096, 256>>>(kv_norm_w);
    // wkv_b nope-transpose (tf32 out)
    wbt_kernel<<<4096, 256>>>(wkv_b_w);
    // q_pe rope + scale into qc[:,512:576] (tf32 out)
    qpe_pack_kernel<<<8192, 256>>>();
    // q_lat = q_nope @ wkv_b[:, :128]^T  (scaled)  -> qc[:, :512] (tf32 out)
    gemm_tf32<<<dim3(4, 16, 32), blk>>>(
        q, 3072, (long long)2048 * 3072, 192,
        wbt, 128, 0, (long long)512 * 128,
        qc, 576, (long long)16 * 2048 * 576, (long long)2048 * 576,
        512, 128, nullptr, SCALE_QK, 4);
    // scores = Qc @ Kc^T  (causal tile skip)
    gemm_tf32<<<dim3(16, 16, 32), blk>>>(
        qc, 576, (long long)16 * 2048 * 576, (long long)2048 * 576,
        kc, 576, (long long)2048 * 576, 0,
        sc, 2048, (long long)16 * 2048 * 2048, (long long)2048 * 2048,
        2048, 576, nullptr, 1.f, 1);
    // softmax (causal + mask, tf32 probs)
    softmax_kernel<<<65536, 256>>>(mask);
    // out_lat = P @ V  (K clamped per 128-row query tile, tf32 out)
    gemm_tf32<<<dim3(4, 16, 32), blk>>>(
        sc, 2048, (long long)16 * 2048 * 2048, (long long)2048 * 2048,
        kvT, 2048, (long long)512 * 2048, 0,
        ol, 512, (long long)16 * 2048 * 512, (long long)2048 * 512,
        512, 2048, nullptr, 1.f, 2 | 4);
    // out_head[t, h*128+d] = out_lat @ wkv_b[:, 128:]^T (tf32 out)
    gemm_tf32<<<dim3(1, 16, 32), blk>>>(
        ol, 512, (long long)16 * 2048 * 512, (long long)2048 * 512,
        wbr + 128 * 512, 512, 0, (long long)256 * 512,
        oh, 2048, (long long)2048 * 2048, 128,
        128, 512, nullptr, 1.f, 4);
    // out = out_head @ wo^T + b (full fp32 out)
    gemm_tf32<<<dim3(16, 32, 1), blk>>>(oh, 2048, 0, 0, wor, 2048, 0, 0,
                                        out, 2048, 0, 0, 2048, 2048, wo_b, 1.f, 0);
}